// round 1
// baseline (speedup 1.0000x reference)
#include <cuda_runtime.h>
#include <math.h>

// ---------------- problem constants ----------------
#define BATCH   32
#define L0      4096
#define L1      2048
#define L2      1024
#define C0      256
#define C1      256
#define C2      512
#define C3      128   // EMB_DIM
#define NCODES  4096
#define NROWS   (BATCH * L2)          // 32768 vq rows
#define BN_EPS  1e-5

// ---------------- device scratch (allocation-free rule: __device__ globals) ---
__device__ float g_wt1[C0 * 3 * C1];         // folded+transposed conv1 weights [ci*3+k][co]
__device__ float g_bb1[C1];
__device__ float g_wt2[C1 * 3 * C2];
__device__ float g_bb2[C2];
__device__ float g_wt3[C2 * 3 * C3];
__device__ float g_bb3[C3];
__device__ float g_h1[(size_t)BATCH * C1 * L1];   // 67 MB
__device__ float g_h2[(size_t)BATCH * C2 * L2];   // 67 MB
__device__ float g_zz[(size_t)NROWS * C3];        // 16.8 MB, row-major [n][d]
__device__ float g_esq[NCODES];
__device__ float g_dummy_codes[NROWS];
__device__ float g_dummy_q[(size_t)NROWS * C3];

// ---------------- prep: fold BN into weights, transpose to [ci*3+k][co] ------
__global__ void fold_kernel(const float* __restrict__ w, const float* __restrict__ bias,
                            const float* __restrict__ g, const float* __restrict__ be,
                            const float* __restrict__ m, const float* __restrict__ v,
                            float* __restrict__ wt, float* __restrict__ bout,
                            int CIN, int COUT)
{
    int idx = blockIdx.x * 256 + threadIdx.x;
    int total = CIN * 3 * COUT;
    if (idx < total) {
        int row = idx / COUT;      // ci*3+k
        int co  = idx - row * COUT;
        float invf = 1.0f;
        if (g) {
            double dinv = (double)g[co] / sqrt((double)v[co] + (double)BN_EPS);
            invf = (float)dinv;
        }
        wt[idx] = w[(size_t)co * (CIN * 3) + row] * invf;
    }
    if (idx < COUT) {
        float bo;
        if (g) {
            double dinv = (double)g[idx] / sqrt((double)v[idx] + (double)BN_EPS);
            bo = (float)((double)bias[idx] * dinv + (double)be[idx] - (double)m[idx] * dinv);
        } else {
            bo = bias[idx];
        }
        bout[idx] = bo;
    }
}

__global__ void esq_kernel(const float* __restrict__ emb)
{
    int j = blockIdx.x * 256 + threadIdx.x;
    if (j < NCODES) {
        const float* e = emb + (size_t)j * C3;
        float s = 0.f;
        #pragma unroll 8
        for (int k = 0; k < C3; ++k) s = fmaf(e[k], e[k], s);
        g_esq[j] = s;
    }
}

// ---------------- conv kernel: 128(co) x 128(t) block tile, 8x8 microtile ----
// Input  X: [BATCH][CIN][LIN]
// Weight Wt: [CIN*3][COUT]  (BN pre-folded)
// Output Y: [BATCH][COUT][LOUT]  (or transposed [BATCH][LOUT][COUT] if TROUT)
template<int CIN, int LIN, int LOUT, int COUT, int STRIDE, bool RELU, bool TROUT>
__global__ __launch_bounds__(256, 2)
void conv_kernel(const float* __restrict__ X, const float* __restrict__ Wt,
                 const float* __restrict__ bias, float* __restrict__ Y)
{
    // sX[k][ci_local][t]: input value feeding tap k of local output t
    __shared__ float sX[3 * 8 * 128];
    __shared__ float sW[8 * 3 * 128];   // [ci_local][k][co] flat = (ci*3+k)*128+co

    const int tid = threadIdx.x;
    const int tx = tid & 15;       // -> t fragment
    const int ty = tid >> 4;       // -> co fragment
    const int t0  = blockIdx.x * 128;
    const int co0 = blockIdx.y * 128;
    const int b   = blockIdx.z;

    const float* xb = X + (size_t)b * CIN * LIN;

    float acc[8][8];
    #pragma unroll
    for (int i = 0; i < 8; ++i)
        #pragma unroll
        for (int j = 0; j < 8; ++j) acc[i][j] = 0.f;

    const int NV = (STRIDE == 2) ? 257 : 130;
    const int GB = (STRIDE == 2) ? (2 * t0 - 1) : (t0 - 1);

    for (int cc = 0; cc < CIN / 8; ++cc) {
        // ---- fill X tile (coalesced gmem, scatter into per-tap arrays) ----
        for (int r = tid; r < 8 * NV; r += 256) {
            int row = r / NV;
            int pos = r - row * NV;
            int gidx = GB + pos;
            float val = (gidx >= 0 && gidx < LIN) ? xb[(size_t)(cc * 8 + row) * LIN + gidx] : 0.f;
            if (STRIDE == 2) {
                if (pos & 1) {
                    sX[1024 + row * 128 + ((pos - 1) >> 1)] = val;     // tap k=1 (even gidx)
                } else {
                    int t = pos >> 1;
                    if (t < 128) sX[row * 128 + t] = val;              // tap k=0
                    if (t >= 1)  sX[2048 + row * 128 + (t - 1)] = val; // tap k=2
                }
            } else {
                if (pos < 128)              sX[row * 128 + pos] = val;            // k=0: x[t-1]
                if (pos >= 1 && pos <= 128) sX[1024 + row * 128 + (pos - 1)] = val; // k=1: x[t]
                if (pos >= 2)               sX[2048 + row * 128 + (pos - 2)] = val; // k=2: x[t+1]
            }
        }
        // ---- fill W tile (flat coalesced copy) ----
        for (int r = tid; r < 3072; r += 256) {
            sW[r] = Wt[(size_t)(cc * 24 + (r >> 7)) * COUT + co0 + (r & 127)];
        }
        __syncthreads();

        // ---- compute ----
        #pragma unroll
        for (int kc = 0; kc < 8; ++kc) {
            #pragma unroll
            for (int k = 0; k < 3; ++k) {
                float4 xa = *(const float4*)&sX[k * 1024 + kc * 128 + tx * 4];
                float4 xc = *(const float4*)&sX[k * 1024 + kc * 128 + 64 + tx * 4];
                float4 wa = *(const float4*)&sW[kc * 384 + k * 128 + ty * 4];
                float4 wc = *(const float4*)&sW[kc * 384 + k * 128 + 64 + ty * 4];
                float xr[8] = {xa.x, xa.y, xa.z, xa.w, xc.x, xc.y, xc.z, xc.w};
                float wr[8] = {wa.x, wa.y, wa.z, wa.w, wc.x, wc.y, wc.z, wc.w};
                #pragma unroll
                for (int i = 0; i < 8; ++i)
                    #pragma unroll
                    for (int j = 0; j < 8; ++j)
                        acc[i][j] = fmaf(wr[i], xr[j], acc[i][j]);
            }
        }
        __syncthreads();
    }

    // ---- epilogue: bias (+folded BN shift), leaky relu, store ----
    #pragma unroll
    for (int i = 0; i < 8; ++i) {
        int co = co0 + ((i < 4) ? (ty * 4 + i) : (64 + ty * 4 + i - 4));
        float bv = bias[co];
        #pragma unroll
        for (int j = 0; j < 8; ++j) {
            int t = t0 + ((j < 4) ? (tx * 4 + j) : (64 + tx * 4 + j - 4));
            float val = acc[i][j] + bv;
            if (RELU) val = (val >= 0.f) ? val : 0.01f * val;
            if (TROUT) Y[((size_t)b * LOUT + t) * COUT + co] = val;
            else       Y[((size_t)b * COUT + co) * LOUT + t] = val;
        }
    }
}

// ---------------- VQ: dist = (||z||^2 + ||e||^2) - 2 z.e ; argmin, first-index ties
__global__ __launch_bounds__(256, 2)
void vq_kernel(const float* __restrict__ Z, const float* __restrict__ E,
               float* __restrict__ codes, float* __restrict__ quant)
{
    __shared__ float z_s[64 * 132];
    __shared__ float e_s[16 * 132];
    __shared__ float a_s[64];
    __shared__ float b_s[128];
    __shared__ int   jf_s[64];

    const int tid = threadIdx.x;
    const int tx = tid & 15;     // code fragment: 8 codes each
    const int ty = tid >> 4;     // row fragment: 4 rows each
    const int n0 = blockIdx.x * 64;

    for (int r = tid; r < 64 * 128; r += 256) {
        int row = r >> 7, k = r & 127;
        z_s[row * 132 + k] = Z[(size_t)(n0 + row) * C3 + k];
    }
    __syncthreads();
    if (tid < 64) {
        const float* zr = &z_s[tid * 132];
        float s = 0.f;
        #pragma unroll 8
        for (int k = 0; k < 128; ++k) s = fmaf(zr[k], zr[k], s);
        a_s[tid] = s;
    }
    __syncthreads();

    float best[4] = {3.4e38f, 3.4e38f, 3.4e38f, 3.4e38f};
    int   bj[4]   = {0, 0, 0, 0};

    for (int j0 = 0; j0 < NCODES; j0 += 128) {
        float acc[4][8];
        #pragma unroll
        for (int v = 0; v < 4; ++v)
            #pragma unroll
            for (int u = 0; u < 8; ++u) acc[v][u] = 0.f;

        for (int kk0 = 0; kk0 < 128; kk0 += 16) {
            __syncthreads();   // protect previous e_s / b_s readers
            for (int r = tid; r < 128 * 16; r += 256) {
                int c = r >> 4, kd = r & 15;
                e_s[kd * 132 + c] = E[(size_t)(j0 + c) * C3 + kk0 + kd];
            }
            if (kk0 == 0 && tid < 128) b_s[tid] = g_esq[j0 + tid];
            __syncthreads();

            #pragma unroll
            for (int kd = 0; kd < 16; ++kd) {
                float4 ea = *(const float4*)&e_s[kd * 132 + tx * 8];
                float4 eb = *(const float4*)&e_s[kd * 132 + tx * 8 + 4];
                float er[8] = {ea.x, ea.y, ea.z, ea.w, eb.x, eb.y, eb.z, eb.w};
                float zr[4];
                #pragma unroll
                for (int v = 0; v < 4; ++v) zr[v] = z_s[(ty * 4 + v) * 132 + kk0 + kd];
                #pragma unroll
                for (int v = 0; v < 4; ++v)
                    #pragma unroll
                    for (int u = 0; u < 8; ++u)
                        acc[v][u] = fmaf(zr[v], er[u], acc[v][u]);
            }
        }

        // dist with the same fp32 expression shape as the reference:
        // (||z||^2 + ||e||^2) - 2*dot   (2*dot exact doubling -> single rounding)
        #pragma unroll
        for (int v = 0; v < 4; ++v) {
            float av = a_s[ty * 4 + v];
            #pragma unroll
            for (int u = 0; u < 8; ++u) {
                float d = (av + b_s[tx * 8 + u]) - 2.0f * acc[v][u];
                int j = j0 + tx * 8 + u;         // ascending j within thread & chunks
                if (d < best[v]) { best[v] = d; bj[v] = j; }  // strict < keeps first index
            }
        }
    }

    // reduce across the 16 tx lanes (same ty -> same half-warp), first-index ties
    #pragma unroll
    for (int v = 0; v < 4; ++v) {
        #pragma unroll
        for (int off = 8; off >= 1; off >>= 1) {
            float ov = __shfl_xor_sync(0xffffffffu, best[v], off);
            int   oj = __shfl_xor_sync(0xffffffffu, bj[v],   off);
            if (ov < best[v] || (ov == best[v] && oj < bj[v])) { best[v] = ov; bj[v] = oj; }
        }
        if (tx == 0) jf_s[ty * 4 + v] = bj[v];
    }
    __syncthreads();

    if (tid < 64) codes[n0 + tid] = (float)jf_s[tid];
    for (int r = tid; r < 64 * 128; r += 256) {
        int row = r >> 7, k = r & 127;
        quant[(size_t)(n0 + row) * C3 + k] = E[(size_t)jf_s[row] * C3 + k];
    }
}

// ---------------- host launch ----------------
static void* sym(const void* s) { void* p = nullptr; cudaGetSymbolAddress(&p, s); return p; }

extern "C" void kernel_launch(void* const* d_in, const int* in_sizes, int n_in,
                              void* d_out, int out_size)
{
    const float* x       = (const float*)d_in[0];
    const float* conv1_w = (const float*)d_in[1];
    const float* conv1_b = (const float*)d_in[2];
    const float* bn1_g   = (const float*)d_in[3];
    const float* bn1_b   = (const float*)d_in[4];
    const float* bn1_m   = (const float*)d_in[5];
    const float* bn1_v   = (const float*)d_in[6];
    const float* conv2_w = (const float*)d_in[7];
    const float* conv2_b = (const float*)d_in[8];
    const float* bn2_g   = (const float*)d_in[9];
    const float* bn2_b   = (const float*)d_in[10];
    const float* bn2_m   = (const float*)d_in[11];
    const float* bn2_v   = (const float*)d_in[12];
    const float* conv3_w = (const float*)d_in[13];
    const float* conv3_b = (const float*)d_in[14];
    const float* emb     = (const float*)d_in[15];

    float* wt1 = (float*)sym(g_wt1);  float* bb1 = (float*)sym(g_bb1);
    float* wt2 = (float*)sym(g_wt2);  float* bb2 = (float*)sym(g_bb2);
    float* wt3 = (float*)sym(g_wt3);  float* bb3 = (float*)sym(g_bb3);
    float* h1  = (float*)sym(g_h1);
    float* h2  = (float*)sym(g_h2);
    float* zz  = (float*)sym(g_zz);

    // output layout: (codes[32768], quantized[4194304]) as float32, concatenated
    float* out = (float*)d_out;
    float* codes_ptr;
    float* quant_ptr;
    const int FULL = NROWS + NROWS * C3;
    if (out_size >= FULL)               { codes_ptr = out; quant_ptr = out + NROWS; }
    else if (out_size == NROWS * C3)    { codes_ptr = (float*)sym(g_dummy_codes); quant_ptr = out; }
    else if (out_size == NROWS)         { codes_ptr = out; quant_ptr = (float*)sym(g_dummy_q); }
    else                                { codes_ptr = out; quant_ptr = out + NROWS; }

    // prep
    fold_kernel<<<(C0 * 3 * C1 + 255) / 256, 256>>>(conv1_w, conv1_b, bn1_g, bn1_b, bn1_m, bn1_v, wt1, bb1, C0, C1);
    fold_kernel<<<(C1 * 3 * C2 + 255) / 256, 256>>>(conv2_w, conv2_b, bn2_g, bn2_b, bn2_m, bn2_v, wt2, bb2, C1, C2);
    fold_kernel<<<(C2 * 3 * C3 + 255) / 256, 256>>>(conv3_w, conv3_b, nullptr, nullptr, nullptr, nullptr, wt3, bb3, C2, C3);
    esq_kernel<<<(NCODES + 255) / 256, 256>>>(emb);

    // encoder
    {
        dim3 g1(L1 / 128, C1 / 128, BATCH);
        conv_kernel<C0, L0, L1, C1, 2, true, false><<<g1, 256>>>(x, wt1, bb1, h1);
    }
    {
        dim3 g2(L2 / 128, C2 / 128, BATCH);
        conv_kernel<C1, L1, L2, C2, 2, true, false><<<g2, 256>>>(h1, wt2, bb2, h2);
    }
    {
        dim3 g3(L2 / 128, C3 / 128, BATCH);
        conv_kernel<C2, L2, L2, C3, 1, false, true><<<g3, 256>>>(h2, wt3, bb3, zz);
    }

    // VQ
    vq_kernel<<<NROWS / 64, 256>>>(zz, emb, codes_ptr, quant_ptr);
}

// round 3
// speedup vs baseline: 1.4139x; 1.4139x over previous
#include <cuda_runtime.h>
#include <cuda_bf16.h>
#include <math.h>
#include <stdint.h>

// ---------------- problem constants ----------------
#define BATCH   32
#define L0      4096
#define L1      2048
#define L2      1024
#define C0      256
#define C1      256
#define C2      512
#define C3      128   // EMB_DIM
#define NCODES  4096
#define NROWS   (BATCH * L2)          // 32768 vq rows
#define BN_EPS  1e-5

// ---------------- device scratch ----------------
__device__ float g_wt1[C0 * 3 * C1];
__device__ float g_bb1[C1];
__device__ float g_wt2[C1 * 3 * C2];
__device__ float g_bb2[C2];
__device__ float g_wt3[C2 * 3 * C3];
__device__ float g_bb3[C3];
__device__ float g_h1[(size_t)BATCH * C1 * L1];
__device__ float g_h2[(size_t)BATCH * C2 * L2];
__device__ float g_zz[(size_t)NROWS * C3];
__device__ float g_esq[NCODES];
__device__ float g_arow[NROWS];
__device__ float g_dummy_codes[NROWS];
__device__ float g_dummy_q[(size_t)NROWS * C3];
// bf16 hi/lo split operands, plain row-major [row][k]
__device__ __nv_bfloat16 g_zhi[(size_t)NROWS * C3];
__device__ __nv_bfloat16 g_zlo[(size_t)NROWS * C3];
__device__ __nv_bfloat16 g_ehi[(size_t)NCODES * C3];
__device__ __nv_bfloat16 g_elo[(size_t)NCODES * C3];

// ---------------- prep kernels (verified R1) ----------------
__global__ void fold_kernel(const float* __restrict__ w, const float* __restrict__ bias,
                            const float* __restrict__ g, const float* __restrict__ be,
                            const float* __restrict__ m, const float* __restrict__ v,
                            float* __restrict__ wt, float* __restrict__ bout,
                            int CIN, int COUT)
{
    int idx = blockIdx.x * 256 + threadIdx.x;
    int total = CIN * 3 * COUT;
    if (idx < total) {
        int row = idx / COUT;
        int co  = idx - row * COUT;
        float invf = 1.0f;
        if (g) {
            double dinv = (double)g[co] / sqrt((double)v[co] + (double)BN_EPS);
            invf = (float)dinv;
        }
        wt[idx] = w[(size_t)co * (CIN * 3) + row] * invf;
    }
    if (idx < COUT) {
        float bo;
        if (g) {
            double dinv = (double)g[idx] / sqrt((double)v[idx] + (double)BN_EPS);
            bo = (float)((double)bias[idx] * dinv + (double)be[idx] - (double)m[idx] * dinv);
        } else {
            bo = bias[idx];
        }
        bout[idx] = bo;
    }
}

__global__ void esq_kernel(const float* __restrict__ emb)
{
    int j = blockIdx.x * 256 + threadIdx.x;
    if (j < NCODES) {
        const float* e = emb + (size_t)j * C3;
        float s = 0.f;
        #pragma unroll 8
        for (int k = 0; k < C3; ++k) s = fmaf(e[k], e[k], s);
        g_esq[j] = s;
    }
}

// ---------------- bf16 hi/lo split writers ----------------
__device__ __forceinline__ void bsplit2(float f, unsigned short& hi, unsigned short& lo)
{
    __nv_bfloat16 b0 = __float2bfloat16_rn(f);
    float r = f - __bfloat162float(b0);
    __nv_bfloat16 b1 = __float2bfloat16_rn(r);
    hi = __bfloat16_as_ushort(b0);
    lo = __bfloat16_as_ushort(b1);
}

__device__ __forceinline__ uint4 pack8u(const unsigned short* s)
{
    uint4 w;
    w.x = (uint32_t)s[0] | ((uint32_t)s[1] << 16);
    w.y = (uint32_t)s[2] | ((uint32_t)s[3] << 16);
    w.z = (uint32_t)s[4] | ((uint32_t)s[5] << 16);
    w.w = (uint32_t)s[6] | ((uint32_t)s[7] << 16);
    return w;
}

__global__ __launch_bounds__(256) void split_z_kernel(const float* __restrict__ zz)
{
    int idx = blockIdx.x * 256 + threadIdx.x;   // NROWS*16 threads
    int row = idx >> 4, gs = idx & 15;
    const float* zr = zz + (size_t)row * C3 + gs * 8;
    float4 p0 = *(const float4*)zr;
    float4 p1 = *(const float4*)(zr + 4);
    float v[8] = {p0.x, p0.y, p0.z, p0.w, p1.x, p1.y, p1.z, p1.w};
    unsigned short h[8], l[8];
    #pragma unroll
    for (int e = 0; e < 8; ++e) bsplit2(v[e], h[e], l[e]);
    ((uint4*)g_zhi)[(size_t)row * 16 + gs] = pack8u(h);
    ((uint4*)g_zlo)[(size_t)row * 16 + gs] = pack8u(l);
    if (gs == 0) {
        const float* zf = zz + (size_t)row * C3;
        float a = 0.f;
        #pragma unroll 8
        for (int k = 0; k < C3; ++k) a = fmaf(zf[k], zf[k], a);
        g_arow[row] = a;
    }
}

__global__ __launch_bounds__(256) void split_e_kernel(const float* __restrict__ emb)
{
    int idx = blockIdx.x * 256 + threadIdx.x;   // NCODES*16 threads
    int row = idx >> 4, gs = idx & 15;
    const float* er = emb + (size_t)row * C3 + gs * 8;
    float4 p0 = *(const float4*)er;
    float4 p1 = *(const float4*)(er + 4);
    float v[8] = {p0.x, p0.y, p0.z, p0.w, p1.x, p1.y, p1.z, p1.w};
    unsigned short h[8], l[8];
    #pragma unroll
    for (int e = 0; e < 8; ++e) bsplit2(v[e], h[e], l[e]);
    ((uint4*)g_ehi)[(size_t)row * 16 + gs] = pack8u(h);
    ((uint4*)g_elo)[(size_t)row * 16 + gs] = pack8u(l);
}

// ---------------- conv kernel (unchanged, verified R1) ----------------
template<int CIN, int LIN, int LOUT, int COUT, int STRIDE, bool RELU, bool TROUT>
__global__ __launch_bounds__(256, 2)
void conv_kernel(const float* __restrict__ X, const float* __restrict__ Wt,
                 const float* __restrict__ bias, float* __restrict__ Y)
{
    __shared__ float sX[3 * 8 * 128];
    __shared__ float sW[8 * 3 * 128];

    const int tid = threadIdx.x;
    const int tx = tid & 15;
    const int ty = tid >> 4;
    const int t0  = blockIdx.x * 128;
    const int co0 = blockIdx.y * 128;
    const int b   = blockIdx.z;

    const float* xb = X + (size_t)b * CIN * LIN;

    float acc[8][8];
    #pragma unroll
    for (int i = 0; i < 8; ++i)
        #pragma unroll
        for (int j = 0; j < 8; ++j) acc[i][j] = 0.f;

    const int NV = (STRIDE == 2) ? 257 : 130;
    const int GB = (STRIDE == 2) ? (2 * t0 - 1) : (t0 - 1);

    for (int cc = 0; cc < CIN / 8; ++cc) {
        for (int r = tid; r < 8 * NV; r += 256) {
            int row = r / NV;
            int pos = r - row * NV;
            int gidx = GB + pos;
            float val = (gidx >= 0 && gidx < LIN) ? xb[(size_t)(cc * 8 + row) * LIN + gidx] : 0.f;
            if (STRIDE == 2) {
                if (pos & 1) {
                    sX[1024 + row * 128 + ((pos - 1) >> 1)] = val;
                } else {
                    int t = pos >> 1;
                    if (t < 128) sX[row * 128 + t] = val;
                    if (t >= 1)  sX[2048 + row * 128 + (t - 1)] = val;
                }
            } else {
                if (pos < 128)              sX[row * 128 + pos] = val;
                if (pos >= 1 && pos <= 128) sX[1024 + row * 128 + (pos - 1)] = val;
                if (pos >= 2)               sX[2048 + row * 128 + (pos - 2)] = val;
            }
        }
        for (int r = tid; r < 3072; r += 256) {
            sW[r] = Wt[(size_t)(cc * 24 + (r >> 7)) * COUT + co0 + (r & 127)];
        }
        __syncthreads();

        #pragma unroll
        for (int kc = 0; kc < 8; ++kc) {
            #pragma unroll
            for (int k = 0; k < 3; ++k) {
                float4 xa = *(const float4*)&sX[k * 1024 + kc * 128 + tx * 4];
                float4 xc = *(const float4*)&sX[k * 1024 + kc * 128 + 64 + tx * 4];
                float4 wa = *(const float4*)&sW[kc * 384 + k * 128 + ty * 4];
                float4 wc = *(const float4*)&sW[kc * 384 + k * 128 + 64 + ty * 4];
                float xr[8] = {xa.x, xa.y, xa.z, xa.w, xc.x, xc.y, xc.z, xc.w};
                float wr[8] = {wa.x, wa.y, wa.z, wa.w, wc.x, wc.y, wc.z, wc.w};
                #pragma unroll
                for (int i = 0; i < 8; ++i)
                    #pragma unroll
                    for (int j = 0; j < 8; ++j)
                        acc[i][j] = fmaf(wr[i], xr[j], acc[i][j]);
            }
        }
        __syncthreads();
    }

    #pragma unroll
    for (int i = 0; i < 8; ++i) {
        int co = co0 + ((i < 4) ? (ty * 4 + i) : (64 + ty * 4 + i - 4));
        float bv = bias[co];
        #pragma unroll
        for (int j = 0; j < 8; ++j) {
            int t = t0 + ((j < 4) ? (tx * 4 + j) : (64 + tx * 4 + j - 4));
            float val = acc[i][j] + bv;
            if (RELU) val = (val >= 0.f) ? val : 0.01f * val;
            if (TROUT) Y[((size_t)b * LOUT + t) * COUT + co] = val;
            else       Y[((size_t)b * COUT + co) * LOUT + t] = val;
        }
    }
}

// ---------------- VQ on mma.sync (HMMA bf16) ----------------
// CTA: 128 rows x 4096 codes, 64-code chunks. bf16x2 split, 3 cross-terms.
// smem layout (dynamic):
//   zh @ 0       : 128 rows x 136 bf16 pad (272B/row)  = 34816
//   zl @ 34816   : same                                 = 34816
//   eh @ 69632   : 64 rows x 136 bf16 pad               = 17408
//   el @ 87040   : same                                 = 17408
//   jf @ 104448  : int[128]                             = 512
//   rv @ 104960  : float[256]                           = 1024
//   rj @ 105984  : int[256]                             = 1024
#define ZH_OFF 0
#define ZL_OFF 34816
#define EH_OFF 69632
#define EL_OFF 87040
#define JF_OFF 104448
#define RV_OFF 104960
#define RJ_OFF 105984
#define VQ_DYN 107520
#define ROWPAD 272   // bytes per padded row (136 bf16)

__device__ __forceinline__ void mma_bf16(float* c, const uint32_t* a, uint32_t b0, uint32_t b1)
{
    asm volatile(
        "mma.sync.aligned.m16n8k16.row.col.f32.bf16.bf16.f32 "
        "{%0,%1,%2,%3}, {%4,%5,%6,%7}, {%8,%9}, {%0,%1,%2,%3};"
        : "+f"(c[0]), "+f"(c[1]), "+f"(c[2]), "+f"(c[3])
        : "r"(a[0]), "r"(a[1]), "r"(a[2]), "r"(a[3]), "r"(b0), "r"(b1));
}

__global__ __launch_bounds__(256, 1)
void vq_mma_kernel(const float* __restrict__ esq, const float* __restrict__ arow,
                   const float* __restrict__ emb,
                   float* __restrict__ codes, float* __restrict__ quant)
{
    extern __shared__ char smc[];
    const int tid = threadIdx.x;
    const int lane = tid & 31;
    const int wid = tid >> 5;
    const int warp_m = wid & 3;          // 4 m-warps: 32 rows each
    const int warp_n = wid >> 2;         // 2 n-warps: 32 codes each (of 64-chunk)
    const int g = lane >> 2;             // groupID 0..7
    const int tq = lane & 3;             // threadID_in_group
    const int n0 = blockIdx.x * 128;
    const int mbase = warp_m * 32;

    // ---- load z tile (hi+lo) into padded smem ----
    for (int i = tid; i < 128 * 32; i += 256) {
        int row = i >> 5, u = i & 31;
        ((uint2*)(smc + ZH_OFF))[row * 34 + u] = ((const uint2*)g_zhi)[(size_t)(n0 + row) * 32 + u];
        ((uint2*)(smc + ZL_OFF))[row * 34 + u] = ((const uint2*)g_zlo)[(size_t)(n0 + row) * 32 + u];
    }

    // per-thread ||z||^2 for the 4 row-slots
    float aval[4];
    #pragma unroll
    for (int s = 0; s < 4; ++s)
        aval[s] = __ldg(&arow[n0 + mbase + (s >> 1) * 16 + (s & 1) * 8 + g]);

    float best[4] = {3.4e38f, 3.4e38f, 3.4e38f, 3.4e38f};
    int   bj[4]   = {0, 0, 0, 0};

    for (int c = 0; c < 64; ++c) {
        __syncthreads();   // previous chunk compute done before overwriting e tile
        for (int i = tid; i < 64 * 32; i += 256) {
            int row = i >> 5, u = i & 31;
            ((uint2*)(smc + EH_OFF))[row * 34 + u] = ((const uint2*)g_ehi)[(size_t)(c * 64 + row) * 32 + u];
            ((uint2*)(smc + EL_OFF))[row * 34 + u] = ((const uint2*)g_elo)[(size_t)(c * 64 + row) * 32 + u];
        }
        __syncthreads();

        float acc[2][4][4];
        #pragma unroll
        for (int mt = 0; mt < 2; ++mt)
            #pragma unroll
            for (int nt = 0; nt < 4; ++nt)
                #pragma unroll
                for (int q = 0; q < 4; ++q) acc[mt][nt][q] = 0.f;

        #pragma unroll
        for (int ks = 0; ks < 8; ++ks) {
            const int k0 = ks * 16;
            uint32_t ah[2][4], al[2][4];
            #pragma unroll
            for (int mt = 0; mt < 2; ++mt) {
                int r0 = mbase + mt * 16 + g;
                int cb = (k0 + tq * 2) * 2;
                ah[mt][0] = *(const uint32_t*)(smc + ZH_OFF + r0 * ROWPAD + cb);
                ah[mt][1] = *(const uint32_t*)(smc + ZH_OFF + (r0 + 8) * ROWPAD + cb);
                ah[mt][2] = *(const uint32_t*)(smc + ZH_OFF + r0 * ROWPAD + cb + 16);
                ah[mt][3] = *(const uint32_t*)(smc + ZH_OFF + (r0 + 8) * ROWPAD + cb + 16);
                al[mt][0] = *(const uint32_t*)(smc + ZL_OFF + r0 * ROWPAD + cb);
                al[mt][1] = *(const uint32_t*)(smc + ZL_OFF + (r0 + 8) * ROWPAD + cb);
                al[mt][2] = *(const uint32_t*)(smc + ZL_OFF + r0 * ROWPAD + cb + 16);
                al[mt][3] = *(const uint32_t*)(smc + ZL_OFF + (r0 + 8) * ROWPAD + cb + 16);
            }
            #pragma unroll
            for (int nt = 0; nt < 4; ++nt) {
                int nrow = warp_n * 32 + nt * 8 + g;
                int cb = (k0 + tq * 2) * 2;
                uint32_t bh0 = *(const uint32_t*)(smc + EH_OFF + nrow * ROWPAD + cb);
                uint32_t bh1 = *(const uint32_t*)(smc + EH_OFF + nrow * ROWPAD + cb + 16);
                uint32_t bl0 = *(const uint32_t*)(smc + EL_OFF + nrow * ROWPAD + cb);
                uint32_t bl1 = *(const uint32_t*)(smc + EL_OFF + nrow * ROWPAD + cb + 16);
                #pragma unroll
                for (int mt = 0; mt < 2; ++mt) {
                    mma_bf16(acc[mt][nt], ah[mt], bh0, bh1);   // hi.hi
                    mma_bf16(acc[mt][nt], ah[mt], bl0, bl1);   // hi.lo
                    mma_bf16(acc[mt][nt], al[mt], bh0, bh1);   // lo.hi
                }
            }
        }

        // epilogue: distance + argmin update (ascending j within thread)
        #pragma unroll
        for (int nt = 0; nt < 4; ++nt) {
            int jb = c * 64 + warp_n * 32 + nt * 8 + tq * 2;
            float e0 = __ldg(&esq[jb]);
            float e1 = __ldg(&esq[jb + 1]);
            #pragma unroll
            for (int mt = 0; mt < 2; ++mt) {
                int s0 = mt * 2, s1 = mt * 2 + 1;
                float d;
                d = (aval[s0] + e0) - 2.0f * acc[mt][nt][0];
                if (d < best[s0]) { best[s0] = d; bj[s0] = jb; }
                d = (aval[s0] + e1) - 2.0f * acc[mt][nt][1];
                if (d < best[s0]) { best[s0] = d; bj[s0] = jb + 1; }
                d = (aval[s1] + e0) - 2.0f * acc[mt][nt][2];
                if (d < best[s1]) { best[s1] = d; bj[s1] = jb; }
                d = (aval[s1] + e1) - 2.0f * acc[mt][nt][3];
                if (d < best[s1]) { best[s1] = d; bj[s1] = jb + 1; }
            }
        }
    }

    // ---- reduce across tq lanes (same rows, different cols) ----
    #pragma unroll
    for (int s = 0; s < 4; ++s) {
        #pragma unroll
        for (int off = 2; off >= 1; off >>= 1) {
            float ov = __shfl_xor_sync(0xffffffffu, best[s], off);
            int   oj = __shfl_xor_sync(0xffffffffu, bj[s],   off);
            if (ov < best[s] || (ov == best[s] && oj < bj[s])) { best[s] = ov; bj[s] = oj; }
        }
    }
    float* rv = (float*)(smc + RV_OFF);
    int*   rj = (int*)(smc + RJ_OFF);
    if (tq == 0) {
        #pragma unroll
        for (int s = 0; s < 4; ++s) {
            int row = mbase + (s >> 1) * 16 + (s & 1) * 8 + g;
            rv[row * 2 + warp_n] = best[s];
            rj[row * 2 + warp_n] = bj[s];
        }
    }
    __syncthreads();

    int* jf = (int*)(smc + JF_OFF);
    if (tid < 128) {
        float v0 = rv[tid * 2], v1 = rv[tid * 2 + 1];
        int   j0 = rj[tid * 2], j1 = rj[tid * 2 + 1];
        int j = (v1 < v0 || (v1 == v0 && j1 < j0)) ? j1 : j0;
        jf[tid] = j;
        codes[n0 + tid] = (float)j;
    }
    __syncthreads();

    for (int i = tid; i < 128 * 32; i += 256) {
        int row = i >> 5, q = i & 31;
        int j = jf[row];
        float4 v = __ldg((const float4*)emb + (size_t)j * 32 + q);
        ((float4*)quant)[(size_t)(n0 + row) * 32 + q] = v;
    }
}

// ---------------- host launch ----------------
static void* sym(const void* s) { void* p = nullptr; cudaGetSymbolAddress(&p, s); return p; }

extern "C" void kernel_launch(void* const* d_in, const int* in_sizes, int n_in,
                              void* d_out, int out_size)
{
    const float* x       = (const float*)d_in[0];
    const float* conv1_w = (const float*)d_in[1];
    const float* conv1_b = (const float*)d_in[2];
    const float* bn1_g   = (const float*)d_in[3];
    const float* bn1_b   = (const float*)d_in[4];
    const float* bn1_m   = (const float*)d_in[5];
    const float* bn1_v   = (const float*)d_in[6];
    const float* conv2_w = (const float*)d_in[7];
    const float* conv2_b = (const float*)d_in[8];
    const float* bn2_g   = (const float*)d_in[9];
    const float* bn2_b   = (const float*)d_in[10];
    const float* bn2_m   = (const float*)d_in[11];
    const float* bn2_v   = (const float*)d_in[12];
    const float* conv3_w = (const float*)d_in[13];
    const float* conv3_b = (const float*)d_in[14];
    const float* emb     = (const float*)d_in[15];

    float* wt1 = (float*)sym(g_wt1);  float* bb1 = (float*)sym(g_bb1);
    float* wt2 = (float*)sym(g_wt2);  float* bb2 = (float*)sym(g_bb2);
    float* wt3 = (float*)sym(g_wt3);  float* bb3 = (float*)sym(g_bb3);
    float* h1  = (float*)sym(g_h1);
    float* h2  = (float*)sym(g_h2);
    float* zz  = (float*)sym(g_zz);
    float* esq = (float*)sym(g_esq);
    float* arw = (float*)sym(g_arow);

    float* out = (float*)d_out;
    float* codes_ptr;
    float* quant_ptr;
    const int FULL = NROWS + NROWS * C3;
    if (out_size >= FULL)            { codes_ptr = out; quant_ptr = out + NROWS; }
    else if (out_size == NROWS * C3) { codes_ptr = (float*)sym(g_dummy_codes); quant_ptr = out; }
    else if (out_size == NROWS)      { codes_ptr = out; quant_ptr = (float*)sym(g_dummy_q); }
    else                             { codes_ptr = out; quant_ptr = out + NROWS; }

    cudaFuncSetAttribute(vq_mma_kernel, cudaFuncAttributeMaxDynamicSharedMemorySize, VQ_DYN);

    // prep
    fold_kernel<<<(C0 * 3 * C1 + 255) / 256, 256>>>(conv1_w, conv1_b, bn1_g, bn1_b, bn1_m, bn1_v, wt1, bb1, C0, C1);
    fold_kernel<<<(C1 * 3 * C2 + 255) / 256, 256>>>(conv2_w, conv2_b, bn2_g, bn2_b, bn2_m, bn2_v, wt2, bb2, C1, C2);
    fold_kernel<<<(C2 * 3 * C3 + 255) / 256, 256>>>(conv3_w, conv3_b, nullptr, nullptr, nullptr, nullptr, wt3, bb3, C2, C3);
    esq_kernel<<<(NCODES + 255) / 256, 256>>>(emb);
    split_e_kernel<<<(NCODES * 16) / 256, 256>>>(emb);

    // encoder
    {
        dim3 g1(L1 / 128, C1 / 128, BATCH);
        conv_kernel<C0, L0, L1, C1, 2, true, false><<<g1, 256>>>(x, wt1, bb1, h1);
    }
    {
        dim3 g2(L2 / 128, C2 / 128, BATCH);
        conv_kernel<C1, L1, L2, C2, 2, true, false><<<g2, 256>>>(h1, wt2, bb2, h2);
    }
    {
        dim3 g3(L2 / 128, C3 / 128, BATCH);
        conv_kernel<C2, L2, L2, C3, 1, false, true><<<g3, 256>>>(h2, wt3, bb3, zz);
    }

    // splits
    split_z_kernel<<<(NROWS * 16) / 256, 256>>>(zz);

    // VQ on tensor cores (legacy mma.sync path)
    vq_mma_kernel<<<NROWS / 128, 256, VQ_DYN>>>(esq, arw, emb, codes_ptr, quant_ptr);
}

// round 9
// speedup vs baseline: 1.4668x; 1.0374x over previous
#include <cuda_runtime.h>
#include <cuda_bf16.h>
#include <math.h>
#include <stdint.h>

// ---------------- problem constants ----------------
#define BATCH   32
#define L0      4096
#define L1      2048
#define L2      1024
#define C0      256
#define C1      256
#define C2      512
#define C3      128   // EMB_DIM
#define NCODES  4096
#define NROWS   (BATCH * L2)
#define BN_EPS  1e-5

// limb-plane element counts
#define XQN  ((size_t)BATCH * L0 * C0)
#define H1N  ((size_t)BATCH * L1 * C1)
#define H2N  ((size_t)BATCH * L2 * C2)
#define W1N  ((size_t)3 * C1 * C0)
#define W2N  ((size_t)3 * C2 * C1)
#define W3N  ((size_t)3 * C3 * C2)

// prescales (power-of-2, >=4x headroom over measured maxima)
#define INV_SX 0.03125f     // S_x = 32
#define INV_SH 0.015625f    // S_h = 64
#define INV_SW 0.5f         // S_w = 2
#define FSCALE1 0.00390625f // 32*2*2^-14
#define FSCALE2 0.0078125f  // 64*2*2^-14
#define FSCALE3 0.0078125f

// ---------------- device scratch ----------------
__device__ float g_bb1[C1];
__device__ float g_bb2[C2];
__device__ float g_bb3[C3];
__device__ float g_h1f[H1N];
__device__ float g_h2f[H2N];
__device__ float g_zz[(size_t)NROWS * C3];
__device__ float g_esq[NCODES];
__device__ float g_arow[NROWS];
__device__ float g_dummy_codes[NROWS];
__device__ float g_dummy_q[(size_t)NROWS * C3];
// int8 limb planes (4 limbs contiguous; host does base+stride arithmetic)
__device__ int8_t g_xq[4 * XQN];
__device__ int8_t g_h1q[4 * H1N];
__device__ int8_t g_h2q[4 * H2N];
__device__ int8_t g_w1q[4 * W1N];
__device__ int8_t g_w2q[4 * W2N];
__device__ int8_t g_w3q[4 * W3N];
// VQ split operands (bf16x2, proven R3)
__device__ __nv_bfloat16 g_zhi[(size_t)NROWS * C3];
__device__ __nv_bfloat16 g_zlo[(size_t)NROWS * C3];
__device__ __nv_bfloat16 g_ehi[(size_t)NCODES * C3];
__device__ __nv_bfloat16 g_elo[(size_t)NCODES * C3];

// ---------------- helpers ----------------
__device__ __forceinline__ void bsplit2(float f, unsigned short& hi, unsigned short& lo)
{
    __nv_bfloat16 b0 = __float2bfloat16_rn(f);
    float r = f - __bfloat162float(b0);
    __nv_bfloat16 b1 = __float2bfloat16_rn(r);
    hi = __bfloat16_as_ushort(b0);
    lo = __bfloat16_as_ushort(b1);
}

__device__ __forceinline__ uint4 pack8u(const unsigned short* s)
{
    uint4 w;
    w.x = (uint32_t)s[0] | ((uint32_t)s[1] << 16);
    w.y = (uint32_t)s[2] | ((uint32_t)s[3] << 16);
    w.z = (uint32_t)s[4] | ((uint32_t)s[5] << 16);
    w.w = (uint32_t)s[6] | ((uint32_t)s[7] << 16);
    return w;
}

__device__ __forceinline__ void mma_bf16(float* c, const uint32_t* a, uint32_t b0, uint32_t b1)
{
    asm volatile(
        "mma.sync.aligned.m16n8k16.row.col.f32.bf16.bf16.f32 "
        "{%0,%1,%2,%3}, {%4,%5,%6,%7}, {%8,%9}, {%0,%1,%2,%3};"
        : "+f"(c[0]), "+f"(c[1]), "+f"(c[2]), "+f"(c[3])
        : "r"(a[0]), "r"(a[1]), "r"(a[2]), "r"(a[3]), "r"(b0), "r"(b1));
}

__device__ __forceinline__ void mma_s8(int* d, const uint32_t* a, uint32_t b0, uint32_t b1)
{
    asm volatile(
        "mma.sync.aligned.m16n8k32.row.col.s32.s8.s8.s32 "
        "{%0,%1,%2,%3}, {%4,%5,%6,%7}, {%8,%9}, {%0,%1,%2,%3};"
        : "+r"(d[0]), "+r"(d[1]), "+r"(d[2]), "+r"(d[3])
        : "r"(a[0]), "r"(a[1]), "r"(a[2]), "r"(a[3]), "r"(b0), "r"(b1));
}

// 4-limb signed-7-bit decomposition: v*invS = sum_i L[i]*2^{-7(i+1)} + O(2^-29)
__device__ __forceinline__ void enc_limbs(float v, float invS, signed char* L)
{
    float u = v * invS;
    float p0 = rintf(u * 128.f);
    float r  = fmaf(p0, -0.0078125f, u);
    float p1 = rintf(r * 16384.f);
    r        = fmaf(p1, -6.103515625e-05f, r);
    float p2 = rintf(r * 2097152.f);
    r        = fmaf(p2, -4.76837158203125e-07f, r);
    float p3 = rintf(r * 268435456.f);
    L[0] = (signed char)(int)p0;
    L[1] = (signed char)(int)p1;
    L[2] = (signed char)(int)p2;
    L[3] = (signed char)(int)p3;
}

// ---------------- prep kernels ----------------
__global__ void fold_enc_kernel(const float* __restrict__ w, const float* __restrict__ bias,
                                const float* __restrict__ g, const float* __restrict__ be,
                                const float* __restrict__ m, const float* __restrict__ v,
                                int8_t* __restrict__ wq, size_t wps,
                                float* __restrict__ bout, int CIN, int COUT)
{
    int idx = blockIdx.x * 256 + threadIdx.x;
    int total = 3 * COUT * CIN;
    if (idx < total) {
        int tap = idx / (COUT * CIN);
        int rem = idx - tap * COUT * CIN;
        int co = rem / CIN;
        int ci = rem - co * CIN;
        float scale = 1.0f;
        if (g) {
            double dinv = (double)g[co] / sqrt((double)v[co] + (double)BN_EPS);
            scale = (float)dinv;
        }
        float val = w[((size_t)co * CIN + ci) * 3 + tap] * scale;
        signed char L[4];
        enc_limbs(val, INV_SW, L);
        #pragma unroll
        for (int p = 0; p < 4; ++p) wq[p * wps + idx] = L[p];
    }
    if (idx < COUT) {
        float bo;
        if (g) {
            double dinv = (double)g[idx] / sqrt((double)v[idx] + (double)BN_EPS);
            bo = (float)((double)bias[idx] * dinv + (double)be[idx] - (double)m[idx] * dinv);
        } else {
            bo = bias[idx];
        }
        bout[idx] = bo;
    }
}

__global__ void esq_kernel(const float* __restrict__ emb)
{
    int j = blockIdx.x * 256 + threadIdx.x;
    if (j < NCODES) {
        const float* e = emb + (size_t)j * C3;
        float s = 0.f;
        #pragma unroll 8
        for (int k = 0; k < C3; ++k) s = fmaf(e[k], e[k], s);
        g_esq[j] = s;
    }
}

// x [b][256][4096] fp32 -> 4 limb planes [b][4096][256] int8 (transpose + encode)
__global__ __launch_bounds__(256) void xenc_kernel(const float* __restrict__ x,
                                                   int8_t* __restrict__ q, size_t qps)
{
    __shared__ float tile[32][33];
    int b = blockIdx.z, t0 = blockIdx.x * 32, c0 = blockIdx.y * 32;
    int tx = threadIdx.x & 31, ty = threadIdx.x >> 5;
    #pragma unroll
    for (int i = 0; i < 4; ++i)
        tile[ty + 8 * i][tx] = x[((size_t)b * C0 + c0 + ty + 8 * i) * L0 + t0 + tx];
    __syncthreads();
    int tl = threadIdx.x & 31;
    int c4 = threadIdx.x >> 5;       // 0..7 -> 4 channels each
    signed char L[4][4];
    #pragma unroll
    for (int k = 0; k < 4; ++k) {
        signed char tmp[4];
        enc_limbs(tile[c4 * 4 + k][tl], INV_SX, tmp);
        #pragma unroll
        for (int p = 0; p < 4; ++p) L[p][k] = tmp[p];
    }
    size_t o = ((size_t)b * L0 + t0 + tl) * C0 + c0 + c4 * 4;
    #pragma unroll
    for (int p = 0; p < 4; ++p)
        *(char4*)(q + p * qps + o) = make_char4(L[p][0], L[p][1], L[p][2], L[p][3]);
}

// fp32 NHWC activations -> 4 limb planes
__global__ __launch_bounds__(256) void henc_kernel(const float* __restrict__ H,
                                                   int8_t* __restrict__ q, size_t qps,
                                                   size_t n4)
{
    size_t i = (size_t)blockIdx.x * 256 + threadIdx.x;
    if (i >= n4) return;
    float4 v = ((const float4*)H)[i];
    signed char L[4][4], tmp[4];
    enc_limbs(v.x, INV_SH, tmp); L[0][0]=tmp[0]; L[1][0]=tmp[1]; L[2][0]=tmp[2]; L[3][0]=tmp[3];
    enc_limbs(v.y, INV_SH, tmp); L[0][1]=tmp[0]; L[1][1]=tmp[1]; L[2][1]=tmp[2]; L[3][1]=tmp[3];
    enc_limbs(v.z, INV_SH, tmp); L[0][2]=tmp[0]; L[1][2]=tmp[1]; L[2][2]=tmp[2]; L[3][2]=tmp[3];
    enc_limbs(v.w, INV_SH, tmp); L[0][3]=tmp[0]; L[1][3]=tmp[1]; L[2][3]=tmp[2]; L[3][3]=tmp[3];
    #pragma unroll
    for (int p = 0; p < 4; ++p)
        ((char4*)(q + p * qps))[i] = make_char4(L[p][0], L[p][1], L[p][2], L[p][3]);
}

// ---------------- conv via exact int8 IMMA, NHWC ----------------
// Y[t][co] = FSCALE * (iacc0 + sum_{c>=1} acc_c * 2^{-7c}) + bias
// Class 0 (the dominant stream) accumulates EXACTLY in persistent int32 via the
// IMMA accumulator itself across all (chunk, tap) iterations -> single exact I2F
// at the epilogue (totals < 2^24). Classes 1..4 keep fp32 chunk-chains (their
// rounding noise is suppressed by CM_c <= 2^-7; <= ~1e-7 in h units).
template<int CIN, int LIN, int LOUT, int COUT, int STRIDE, bool RELU>
__global__ __launch_bounds__(256, 1)
void conv_imma_kernel(const int8_t* __restrict__ Xq, size_t xps,
                      const int8_t* __restrict__ Wq, size_t wps,
                      const float* __restrict__ bias, float fscale,
                      float* __restrict__ Yf)
{
    constexpr int NTR = STRIDE * 128 + 2;
    constexpr int RB = 36;                 // 32 int8 + 4B pad
    __shared__ int8_t sA[4][NTR * RB];
    __shared__ int8_t sB[4][64 * RB];

    const int tid = threadIdx.x;
    const int lane = tid & 31;
    const int wid = tid >> 5;
    const int warpm = wid & 3;
    const int warpn = wid >> 2;
    const int g = lane >> 2;
    const int tq = lane & 3;
    const int t0  = blockIdx.x * 128;
    const int co0 = blockIdx.y * 64;
    const int bb  = blockIdx.z;
    const int GB  = STRIDE * t0 - 1;

    // class-pair tables for classes 1..4 (i+j = c), class 0 handled separately
    const int PI[12] = {0,1, 0,1,2, 0,1,2,3, 1,2,3};
    const int PJ[12] = {1,0, 2,1,0, 3,2,1,0, 3,2,1};
    const int CS[5]  = {0, 2, 5, 9, 12};
    const float CM[4] = {0.0078125f, 6.103515625e-05f,
                         4.76837158203125e-07f, 3.7252902984619140625e-09f};

    float acc[2][4][4];     // classes 1..4, CM-weighted
    int   iacc[2][4][4];    // class 0, exact int32
    #pragma unroll
    for (int mt = 0; mt < 2; ++mt)
        #pragma unroll
        for (int nt = 0; nt < 4; ++nt)
            #pragma unroll
            for (int q = 0; q < 4; ++q) { acc[mt][nt][q] = 0.f; iacc[mt][nt][q] = 0; }

    for (int cc = 0; cc < CIN / 32; ++cc) {
        __syncthreads();
        // ---- A: NTR rows x 32 int8 x 4 limbs ----
        for (int i = tid; i < NTR * 8; i += 256) {
            int r = i >> 3, u = i & 7;
            int grow = GB + r;
            bool ok = (grow >= 0 && grow < LIN);
            size_t bidx = ok ? ((((size_t)bb * LIN + grow) * CIN + cc * 32) >> 2) + u : 0;
            #pragma unroll
            for (int p = 0; p < 4; ++p) {
                uint32_t v = ok ? ((const uint32_t*)(Xq + p * xps))[bidx] : 0u;
                *(uint32_t*)&sA[p][r * RB + u * 4] = v;
            }
        }
        #pragma unroll
        for (int tap = 0; tap < 3; ++tap) {
            __syncthreads();
            // ---- B[tap]: 64 co x 32 int8 x 4 limbs ----
            for (int i = tid; i < 64 * 8; i += 256) {
                int r = i >> 3, u = i & 7;
                size_t bidx = ((((size_t)tap * COUT + co0 + r) * CIN + cc * 32) >> 2) + u;
                #pragma unroll
                for (int p = 0; p < 4; ++p)
                    *(uint32_t*)&sB[p][r * RB + u * 4] = ((const uint32_t*)(Wq + p * wps))[bidx];
            }
            __syncthreads();

            // ---- A fragments: [limb][mt][4] ----
            uint32_t af[4][2][4];
            #pragma unroll
            for (int mt = 0; mt < 2; ++mt) {
                int tl = warpm * 32 + mt * 16 + g;
                int ra = STRIDE * tl + tap;
                int ra8 = ra + 8 * STRIDE;
                #pragma unroll
                for (int p = 0; p < 4; ++p) {
                    af[p][mt][0] = *(const uint32_t*)&sA[p][ra  * RB + tq * 4];
                    af[p][mt][1] = *(const uint32_t*)&sA[p][ra8 * RB + tq * 4];
                    af[p][mt][2] = *(const uint32_t*)&sA[p][ra  * RB + tq * 4 + 16];
                    af[p][mt][3] = *(const uint32_t*)&sA[p][ra8 * RB + tq * 4 + 16];
                }
            }
            #pragma unroll
            for (int nt = 0; nt < 4; ++nt) {
                int rb = warpn * 32 + nt * 8 + g;
                uint32_t bf[4][2];
                #pragma unroll
                for (int p = 0; p < 4; ++p) {
                    bf[p][0] = *(const uint32_t*)&sB[p][rb * RB + tq * 4];
                    bf[p][1] = *(const uint32_t*)&sB[p][rb * RB + tq * 4 + 16];
                }
                // class 0: accumulate exactly in persistent int32 (no rounding ever)
                mma_s8(iacc[0][nt], af[0][0], bf[0][0], bf[0][1]);
                mma_s8(iacc[1][nt], af[0][1], bf[0][0], bf[0][1]);
                // classes 1..4: fp32 chunk-chains (noise suppressed by CM_c)
                #pragma unroll
                for (int c = 0; c < 4; ++c) {
                    int d0[4] = {0, 0, 0, 0};
                    int d1[4] = {0, 0, 0, 0};
                    #pragma unroll
                    for (int pr = 0; pr < 12; ++pr) {
                        if (pr >= CS[c] && pr < CS[c + 1]) {
                            mma_s8(d0, af[PI[pr]][0], bf[PJ[pr]][0], bf[PJ[pr]][1]);
                            mma_s8(d1, af[PI[pr]][1], bf[PJ[pr]][0], bf[PJ[pr]][1]);
                        }
                    }
                    float m = CM[c];
                    #pragma unroll
                    for (int q = 0; q < 4; ++q) {
                        acc[0][nt][q] = fmaf(__int2float_rn(d0[q]), m, acc[0][nt][q]);
                        acc[1][nt][q] = fmaf(__int2float_rn(d1[q]), m, acc[1][nt][q]);
                    }
                }
            }
        }
    }

    // ---- epilogue: exact class-0 I2F + class 1-4 + scale + bias + leaky relu ----
    #pragma unroll
    for (int nt = 0; nt < 4; ++nt) {
        int cog = co0 + warpn * 32 + nt * 8 + tq * 2;
        float b0 = __ldg(&bias[cog]);
        float b1 = __ldg(&bias[cog + 1]);
        #pragma unroll
        for (int mt = 0; mt < 2; ++mt) {
            #pragma unroll
            for (int half = 0; half < 2; ++half) {
                int t = t0 + warpm * 32 + mt * 16 + g + half * 8;
                float s0 = __int2float_rn(iacc[mt][nt][half * 2])     + acc[mt][nt][half * 2];
                float s1 = __int2float_rn(iacc[mt][nt][half * 2 + 1]) + acc[mt][nt][half * 2 + 1];
                float v0 = fmaf(s0, fscale, b0);
                float v1 = fmaf(s1, fscale, b1);
                if (RELU) {
                    v0 = (v0 >= 0.f) ? v0 : 0.01f * v0;
                    v1 = (v1 >= 0.f) ? v1 : 0.01f * v1;
                }
                *(float2*)(Yf + ((size_t)bb * LOUT + t) * COUT + cog) = make_float2(v0, v1);
            }
        }
    }
}

// ---------------- VQ splits (verified R3) ----------------
__global__ __launch_bounds__(256) void split_z_kernel(const float* __restrict__ zz)
{
    int idx = blockIdx.x * 256 + threadIdx.x;
    int row = idx >> 4, gs = idx & 15;
    const float* zr = zz + (size_t)row * C3 + gs * 8;
    float4 p0 = *(const float4*)zr;
    float4 p1 = *(const float4*)(zr + 4);
    float v[8] = {p0.x, p0.y, p0.z, p0.w, p1.x, p1.y, p1.z, p1.w};
    unsigned short h[8], l[8];
    #pragma unroll
    for (int e = 0; e < 8; ++e) bsplit2(v[e], h[e], l[e]);
    ((uint4*)g_zhi)[(size_t)row * 16 + gs] = pack8u(h);
    ((uint4*)g_zlo)[(size_t)row * 16 + gs] = pack8u(l);
    if (gs == 0) {
        const float* zf = zz + (size_t)row * C3;
        float a = 0.f;
        #pragma unroll 8
        for (int k = 0; k < C3; ++k) a = fmaf(zf[k], zf[k], a);
        g_arow[row] = a;
    }
}

__global__ __launch_bounds__(256) void split_e_kernel(const float* __restrict__ emb)
{
    int idx = blockIdx.x * 256 + threadIdx.x;
    int row = idx >> 4, gs = idx & 15;
    const float* er = emb + (size_t)row * C3 + gs * 8;
    float4 p0 = *(const float4*)er;
    float4 p1 = *(const float4*)(er + 4);
    float v[8] = {p0.x, p0.y, p0.z, p0.w, p1.x, p1.y, p1.z, p1.w};
    unsigned short h[8], l[8];
    #pragma unroll
    for (int e = 0; e < 8; ++e) bsplit2(v[e], h[e], l[e]);
    ((uint4*)g_ehi)[(size_t)row * 16 + gs] = pack8u(h);
    ((uint4*)g_elo)[(size_t)row * 16 + gs] = pack8u(l);
}

// ---------------- VQ on mma.sync (verified R3, unchanged) ----------------
#define ZH_OFF 0
#define ZL_OFF 34816
#define EH_OFF 69632
#define EL_OFF 87040
#define JF_OFF 104448
#define RV_OFF 104960
#define RJ_OFF 105984
#define VQ_DYN 107520
#define ROWPAD 272

__global__ __launch_bounds__(256, 1)
void vq_mma_kernel(const float* __restrict__ esq, const float* __restrict__ arow,
                   const float* __restrict__ emb,
                   float* __restrict__ codes, float* __restrict__ quant)
{
    extern __shared__ char smc[];
    const int tid = threadIdx.x;
    const int lane = tid & 31;
    const int wid = tid >> 5;
    const int warp_m = wid & 3;
    const int warp_n = wid >> 2;
    const int g = lane >> 2;
    const int tq = lane & 3;
    const int n0 = blockIdx.x * 128;
    const int mbase = warp_m * 32;

    for (int i = tid; i < 128 * 32; i += 256) {
        int row = i >> 5, u = i & 31;
        ((uint2*)(smc + ZH_OFF))[row * 34 + u] = ((const uint2*)g_zhi)[(size_t)(n0 + row) * 32 + u];
        ((uint2*)(smc + ZL_OFF))[row * 34 + u] = ((const uint2*)g_zlo)[(size_t)(n0 + row) * 32 + u];
    }

    float aval[4];
    #pragma unroll
    for (int s = 0; s < 4; ++s)
        aval[s] = __ldg(&arow[n0 + mbase + (s >> 1) * 16 + (s & 1) * 8 + g]);

    float best[4] = {3.4e38f, 3.4e38f, 3.4e38f, 3.4e38f};
    int   bj[4]   = {0, 0, 0, 0};

    for (int c = 0; c < 64; ++c) {
        __syncthreads();
        for (int i = tid; i < 64 * 32; i += 256) {
            int row = i >> 5, u = i & 31;
            ((uint2*)(smc + EH_OFF))[row * 34 + u] = ((const uint2*)g_ehi)[(size_t)(c * 64 + row) * 32 + u];
            ((uint2*)(smc + EL_OFF))[row * 34 + u] = ((const uint2*)g_elo)[(size_t)(c * 64 + row) * 32 + u];
        }
        __syncthreads();

        float acc[2][4][4];
        #pragma unroll
        for (int mt = 0; mt < 2; ++mt)
            #pragma unroll
            for (int nt = 0; nt < 4; ++nt)
                #pragma unroll
                for (int q = 0; q < 4; ++q) acc[mt][nt][q] = 0.f;

        #pragma unroll
        for (int ks = 0; ks < 8; ++ks) {
            const int k0 = ks * 16;
            uint32_t ah[2][4], al[2][4];
            #pragma unroll
            for (int mt = 0; mt < 2; ++mt) {
                int r0 = mbase + mt * 16 + g;
                int cb = (k0 + tq * 2) * 2;
                ah[mt][0] = *(const uint32_t*)(smc + ZH_OFF + r0 * ROWPAD + cb);
                ah[mt][1] = *(const uint32_t*)(smc + ZH_OFF + (r0 + 8) * ROWPAD + cb);
                ah[mt][2] = *(const uint32_t*)(smc + ZH_OFF + r0 * ROWPAD + cb + 16);
                ah[mt][3] = *(const uint32_t*)(smc + ZH_OFF + (r0 + 8) * ROWPAD + cb + 16);
                al[mt][0] = *(const uint32_t*)(smc + ZL_OFF + r0 * ROWPAD + cb);
                al[mt][1] = *(const uint32_t*)(smc + ZL_OFF + (r0 + 8) * ROWPAD + cb);
                al[mt][2] = *(const uint32_t*)(smc + ZL_OFF + r0 * ROWPAD + cb + 16);
                al[mt][3] = *(const uint32_t*)(smc + ZL_OFF + (r0 + 8) * ROWPAD + cb + 16);
            }
            #pragma unroll
            for (int nt = 0; nt < 4; ++nt) {
                int nrow = warp_n * 32 + nt * 8 + g;
                int cb = (k0 + tq * 2) * 2;
                uint32_t bh0 = *(const uint32_t*)(smc + EH_OFF + nrow * ROWPAD + cb);
                uint32_t bh1 = *(const uint32_t*)(smc + EH_OFF + nrow * ROWPAD + cb + 16);
                uint32_t bl0 = *(const uint32_t*)(smc + EL_OFF + nrow * ROWPAD + cb);
                uint32_t bl1 = *(const uint32_t*)(smc + EL_OFF + nrow * ROWPAD + cb + 16);
                #pragma unroll
                for (int mt = 0; mt < 2; ++mt) {
                    mma_bf16(acc[mt][nt], ah[mt], bh0, bh1);
                    mma_bf16(acc[mt][nt], ah[mt], bl0, bl1);
                    mma_bf16(acc[mt][nt], al[mt], bh0, bh1);
                }
            }
        }

        #pragma unroll
        for (int nt = 0; nt < 4; ++nt) {
            int jb = c * 64 + warp_n * 32 + nt * 8 + tq * 2;
            float e0 = __ldg(&esq[jb]);
            float e1 = __ldg(&esq[jb + 1]);
            #pragma unroll
            for (int mt = 0; mt < 2; ++mt) {
                int s0 = mt * 2, s1 = mt * 2 + 1;
                float d;
                d = (aval[s0] + e0) - 2.0f * acc[mt][nt][0];
                if (d < best[s0]) { best[s0] = d; bj[s0] = jb; }
                d = (aval[s0] + e1) - 2.0f * acc[mt][nt][1];
                if (d < best[s0]) { best[s0] = d; bj[s0] = jb + 1; }
                d = (aval[s1] + e0) - 2.0f * acc[mt][nt][2];
                if (d < best[s1]) { best[s1] = d; bj[s1] = jb; }
                d = (aval[s1] + e1) - 2.0f * acc[mt][nt][3];
                if (d < best[s1]) { best[s1] = d; bj[s1] = jb + 1; }
            }
        }
    }

    #pragma unroll
    for (int s = 0; s < 4; ++s) {
        #pragma unroll
        for (int off = 2; off >= 1; off >>= 1) {
            float ov = __shfl_xor_sync(0xffffffffu, best[s], off);
            int   oj = __shfl_xor_sync(0xffffffffu, bj[s],   off);
            if (ov < best[s] || (ov == best[s] && oj < bj[s])) { best[s] = ov; bj[s] = oj; }
        }
    }
    float* rv = (float*)(smc + RV_OFF);
    int*   rj = (int*)(smc + RJ_OFF);
    if (tq == 0) {
        #pragma unroll
        for (int s = 0; s < 4; ++s) {
            int row = mbase + (s >> 1) * 16 + (s & 1) * 8 + g;
            rv[row * 2 + warp_n] = best[s];
            rj[row * 2 + warp_n] = bj[s];
        }
    }
    __syncthreads();

    int* jf = (int*)(smc + JF_OFF);
    if (tid < 128) {
        float v0 = rv[tid * 2], v1 = rv[tid * 2 + 1];
        int   j0 = rj[tid * 2], j1 = rj[tid * 2 + 1];
        int j = (v1 < v0 || (v1 == v0 && j1 < j0)) ? j1 : j0;
        jf[tid] = j;
        codes[n0 + tid] = (float)j;
    }
    __syncthreads();

    for (int i = tid; i < 128 * 32; i += 256) {
        int row = i >> 5, q = i & 31;
        int j = jf[row];
        float4 v = __ldg((const float4*)emb + (size_t)j * 32 + q);
        ((float4*)quant)[(size_t)(n0 + row) * 32 + q] = v;
    }
}

// ---------------- host launch ----------------
static void* sym(const void* s) { void* p = nullptr; cudaGetSymbolAddress(&p, s); return p; }

extern "C" void kernel_launch(void* const* d_in, const int* in_sizes, int n_in,
                              void* d_out, int out_size)
{
    const float* x       = (const float*)d_in[0];
    const float* conv1_w = (const float*)d_in[1];
    const float* conv1_b = (const float*)d_in[2];
    const float* bn1_g   = (const float*)d_in[3];
    const float* bn1_b   = (const float*)d_in[4];
    const float* bn1_m   = (const float*)d_in[5];
    const float* bn1_v   = (const float*)d_in[6];
    const float* conv2_w = (const float*)d_in[7];
    const float* conv2_b = (const float*)d_in[8];
    const float* bn2_g   = (const float*)d_in[9];
    const float* bn2_b   = (const float*)d_in[10];
    const float* bn2_m   = (const float*)d_in[11];
    const float* bn2_v   = (const float*)d_in[12];
    const float* conv3_w = (const float*)d_in[13];
    const float* conv3_b = (const float*)d_in[14];
    const float* emb     = (const float*)d_in[15];

    float* bb1 = (float*)sym(g_bb1);
    float* bb2 = (float*)sym(g_bb2);
    float* bb3 = (float*)sym(g_bb3);
    float* h1f = (float*)sym(g_h1f);
    float* h2f = (float*)sym(g_h2f);
    float* zz  = (float*)sym(g_zz);
    float* esq = (float*)sym(g_esq);
    float* arw = (float*)sym(g_arow);
    int8_t* xq  = (int8_t*)sym(g_xq);
    int8_t* h1q = (int8_t*)sym(g_h1q);
    int8_t* h2q = (int8_t*)sym(g_h2q);
    int8_t* w1q = (int8_t*)sym(g_w1q);
    int8_t* w2q = (int8_t*)sym(g_w2q);
    int8_t* w3q = (int8_t*)sym(g_w3q);

    float* out = (float*)d_out;
    float* codes_ptr;
    float* quant_ptr;
    const int FULL = NROWS + NROWS * C3;
    if (out_size >= FULL)            { codes_ptr = out; quant_ptr = out + NROWS; }
    else if (out_size == NROWS * C3) { codes_ptr = (float*)sym(g_dummy_codes); quant_ptr = out; }
    else if (out_size == NROWS)      { codes_ptr = out; quant_ptr = (float*)sym(g_dummy_q); }
    else                             { codes_ptr = out; quant_ptr = out + NROWS; }

    cudaFuncSetAttribute(vq_mma_kernel, cudaFuncAttributeMaxDynamicSharedMemorySize, VQ_DYN);

    // prep: weights -> limb planes, VQ tables
    fold_enc_kernel<<<(3 * C1 * C0 + 255) / 256, 256>>>(conv1_w, conv1_b, bn1_g, bn1_b, bn1_m, bn1_v,
                                                        w1q, W1N, bb1, C0, C1);
    fold_enc_kernel<<<(3 * C2 * C1 + 255) / 256, 256>>>(conv2_w, conv2_b, bn2_g, bn2_b, bn2_m, bn2_v,
                                                        w2q, W2N, bb2, C1, C2);
    fold_enc_kernel<<<(3 * C3 * C2 + 255) / 256, 256>>>(conv3_w, conv3_b, nullptr, nullptr, nullptr, nullptr,
                                                        w3q, W3N, bb3, C2, C3);
    esq_kernel<<<(NCODES + 255) / 256, 256>>>(emb);
    split_e_kernel<<<(NCODES * 16) / 256, 256>>>(emb);

    // x -> transposed limb planes
    {
        dim3 gx(L0 / 32, C0 / 32, BATCH);
        xenc_kernel<<<gx, 256>>>(x, xq, XQN);
    }

    // encoder: exact int8 IMMA convs (class-0 int-exact)
    {
        dim3 g1(L1 / 128, C1 / 64, BATCH);
        conv_imma_kernel<C0, L0, L1, C1, 2, true><<<g1, 256>>>(xq, XQN, w1q, W1N, bb1, FSCALE1, h1f);
    }
    henc_kernel<<<(unsigned)((H1N / 4 + 255) / 256), 256>>>(h1f, h1q, H1N, H1N / 4);
    {
        dim3 g2(L2 / 128, C2 / 64, BATCH);
        conv_imma_kernel<C1, L1, L2, C2, 2, true><<<g2, 256>>>(h1q, H1N, w2q, W2N, bb2, FSCALE2, h2f);
    }
    henc_kernel<<<(unsigned)((H2N / 4 + 255) / 256), 256>>>(h2f, h2q, H2N, H2N / 4);
    {
        dim3 g3(L2 / 128, C3 / 64, BATCH);
        conv_imma_kernel<C2, L2, L2, C3, 1, false><<<g3, 256>>>(h2q, H2N, w3q, W3N, bb3, FSCALE3, zz);
    }

    // VQ (proven path)
    split_z_kernel<<<(NROWS * 16) / 256, 256>>>(zz);
    vq_mma_kernel<<<NROWS / 128, 256, VQ_DYN>>>(esq, arw, emb, codes_ptr, quant_ptr);
}

// round 10
// speedup vs baseline: 1.6251x; 1.1080x over previous
#include <cuda_runtime.h>
#include <cuda_bf16.h>
#include <math.h>
#include <stdint.h>

// ---------------- problem constants ----------------
#define BATCH   32
#define L0      4096
#define L1      2048
#define L2      1024
#define C0      256
#define C1      256
#define C2      512
#define C3      128   // EMB_DIM
#define NCODES  4096
#define NROWS   (BATCH * L2)
#define BN_EPS  1e-5

// limb-plane element counts
#define XQN  ((size_t)BATCH * L0 * C0)
#define H1N  ((size_t)BATCH * L1 * C1)
#define H2N  ((size_t)BATCH * L2 * C2)
#define W1N  ((size_t)3 * C1 * C0)
#define W2N  ((size_t)3 * C2 * C1)
#define W3N  ((size_t)3 * C3 * C2)

// prescales (power-of-2, >=4x headroom over measured maxima)
#define INV_SX 0.03125f     // S_x = 32
#define INV_SH 0.015625f    // S_h = 64
#define INV_SW 0.5f         // S_w = 2
#define FSCALE1 0.00390625f // 32*2*2^-14
#define FSCALE2 0.0078125f  // 64*2*2^-14
#define FSCALE3 0.0078125f

// ---------------- device scratch ----------------
__device__ float g_bb1[C1];
__device__ float g_bb2[C2];
__device__ float g_bb3[C3];
__device__ float g_zz[(size_t)NROWS * C3];
__device__ float g_esq[NCODES];
__device__ float g_arow[NROWS];
__device__ float g_dummy_codes[NROWS];
__device__ float g_dummy_q[(size_t)NROWS * C3];
// int8 limb planes
__device__ int8_t g_xq[4 * XQN];
__device__ int8_t g_h1q[4 * H1N];
__device__ int8_t g_h2q[4 * H2N];
__device__ int8_t g_w1q[4 * W1N];
__device__ int8_t g_w2q[4 * W2N];
__device__ int8_t g_w3q[4 * W3N];
// VQ split operands (bf16x2, proven R3)
__device__ __nv_bfloat16 g_zhi[(size_t)NROWS * C3];
__device__ __nv_bfloat16 g_zlo[(size_t)NROWS * C3];
__device__ __nv_bfloat16 g_ehi[(size_t)NCODES * C3];
__device__ __nv_bfloat16 g_elo[(size_t)NCODES * C3];

// ---------------- helpers ----------------
__device__ __forceinline__ void bsplit2(float f, unsigned short& hi, unsigned short& lo)
{
    __nv_bfloat16 b0 = __float2bfloat16_rn(f);
    float r = f - __bfloat162float(b0);
    __nv_bfloat16 b1 = __float2bfloat16_rn(r);
    hi = __bfloat16_as_ushort(b0);
    lo = __bfloat16_as_ushort(b1);
}

__device__ __forceinline__ uint4 pack8u(const unsigned short* s)
{
    uint4 w;
    w.x = (uint32_t)s[0] | ((uint32_t)s[1] << 16);
    w.y = (uint32_t)s[2] | ((uint32_t)s[3] << 16);
    w.z = (uint32_t)s[4] | ((uint32_t)s[5] << 16);
    w.w = (uint32_t)s[6] | ((uint32_t)s[7] << 16);
    return w;
}

__device__ __forceinline__ void mma_bf16(float* c, const uint32_t* a, uint32_t b0, uint32_t b1)
{
    asm volatile(
        "mma.sync.aligned.m16n8k16.row.col.f32.bf16.bf16.f32 "
        "{%0,%1,%2,%3}, {%4,%5,%6,%7}, {%8,%9}, {%0,%1,%2,%3};"
        : "+f"(c[0]), "+f"(c[1]), "+f"(c[2]), "+f"(c[3])
        : "r"(a[0]), "r"(a[1]), "r"(a[2]), "r"(a[3]), "r"(b0), "r"(b1));
}

__device__ __forceinline__ void mma_s8(int* d, const uint32_t* a, uint32_t b0, uint32_t b1)
{
    asm volatile(
        "mma.sync.aligned.m16n8k32.row.col.s32.s8.s8.s32 "
        "{%0,%1,%2,%3}, {%4,%5,%6,%7}, {%8,%9}, {%0,%1,%2,%3};"
        : "+r"(d[0]), "+r"(d[1]), "+r"(d[2]), "+r"(d[3])
        : "r"(a[0]), "r"(a[1]), "r"(a[2]), "r"(a[3]), "r"(b0), "r"(b1));
}

// 4-limb signed-7-bit decomposition: v*invS = sum_i L[i]*2^{-7(i+1)} + O(2^-29)
__device__ __forceinline__ void enc_limbs(float v, float invS, signed char* L)
{
    float u = v * invS;
    float p0 = rintf(u * 128.f);
    float r  = fmaf(p0, -0.0078125f, u);
    float p1 = rintf(r * 16384.f);
    r        = fmaf(p1, -6.103515625e-05f, r);
    float p2 = rintf(r * 2097152.f);
    r        = fmaf(p2, -4.76837158203125e-07f, r);
    float p3 = rintf(r * 268435456.f);
    L[0] = (signed char)(int)p0;
    L[1] = (signed char)(int)p1;
    L[2] = (signed char)(int)p2;
    L[3] = (signed char)(int)p3;
}

// ---------------- prep kernels ----------------
__global__ void fold_enc_kernel(const float* __restrict__ w, const float* __restrict__ bias,
                                const float* __restrict__ g, const float* __restrict__ be,
                                const float* __restrict__ m, const float* __restrict__ v,
                                int8_t* __restrict__ wq, size_t wps,
                                float* __restrict__ bout, int CIN, int COUT)
{
    int idx = blockIdx.x * 256 + threadIdx.x;
    int total = 3 * COUT * CIN;
    if (idx < total) {
        int tap = idx / (COUT * CIN);
        int rem = idx - tap * COUT * CIN;
        int co = rem / CIN;
        int ci = rem - co * CIN;
        float scale = 1.0f;
        if (g) {
            double dinv = (double)g[co] / sqrt((double)v[co] + (double)BN_EPS);
            scale = (float)dinv;
        }
        float val = w[((size_t)co * CIN + ci) * 3 + tap] * scale;
        signed char L[4];
        enc_limbs(val, INV_SW, L);
        #pragma unroll
        for (int p = 0; p < 4; ++p) wq[p * wps + idx] = L[p];
    }
    if (idx < COUT) {
        float bo;
        if (g) {
            double dinv = (double)g[idx] / sqrt((double)v[idx] + (double)BN_EPS);
            bo = (float)((double)bias[idx] * dinv + (double)be[idx] - (double)m[idx] * dinv);
        } else {
            bo = bias[idx];
        }
        bout[idx] = bo;
    }
}

__global__ void esq_kernel(const float* __restrict__ emb)
{
    int j = blockIdx.x * 256 + threadIdx.x;
    if (j < NCODES) {
        const float* e = emb + (size_t)j * C3;
        float s = 0.f;
        #pragma unroll 8
        for (int k = 0; k < C3; ++k) s = fmaf(e[k], e[k], s);
        g_esq[j] = s;
    }
}

// x [b][256][4096] fp32 -> 4 limb planes [b][4096][256] int8 (transpose + encode)
__global__ __launch_bounds__(256) void xenc_kernel(const float* __restrict__ x,
                                                   int8_t* __restrict__ q, size_t qps)
{
    __shared__ float tile[32][33];
    int b = blockIdx.z, t0 = blockIdx.x * 32, c0 = blockIdx.y * 32;
    int tx = threadIdx.x & 31, ty = threadIdx.x >> 5;
    #pragma unroll
    for (int i = 0; i < 4; ++i)
        tile[ty + 8 * i][tx] = x[((size_t)b * C0 + c0 + ty + 8 * i) * L0 + t0 + tx];
    __syncthreads();
    int tl = threadIdx.x & 31;
    int c4 = threadIdx.x >> 5;
    signed char L[4][4];
    #pragma unroll
    for (int k = 0; k < 4; ++k) {
        signed char tmp[4];
        enc_limbs(tile[c4 * 4 + k][tl], INV_SX, tmp);
        #pragma unroll
        for (int p = 0; p < 4; ++p) L[p][k] = tmp[p];
    }
    size_t o = ((size_t)b * L0 + t0 + tl) * C0 + c0 + c4 * 4;
    #pragma unroll
    for (int p = 0; p < 4; ++p)
        *(char4*)(q + p * qps + o) = make_char4(L[p][0], L[p][1], L[p][2], L[p][3]);
}

// ---------------- conv via exact int8 IMMA v2 ----------------
// 512 threads / 16 warps (4 warpm x 4 warpn), CTA tile 128t x 64co, warp m32 x n16.
// Classes 0,1 in persistent int32 (exact); classes 2..4 merged fp32 (weights 2^-14/-21/-28).
// All 3 B taps staged per ci-chunk (2 syncs per chunk). Optional fused limb-encode output.
template<int CIN, int LIN, int LOUT, int COUT, int STRIDE, bool RELU, bool SPLITOUT>
__global__ __launch_bounds__(512, 1)
void conv_imma2_kernel(const int8_t* __restrict__ Xq, size_t xps,
                       const int8_t* __restrict__ Wq, size_t wps,
                       const float* __restrict__ bias, float fscale, float invSo,
                       int8_t* __restrict__ Yq, size_t yps,
                       float* __restrict__ Yf)
{
    constexpr int NTR = STRIDE * 128 + 2;
    constexpr int RB = 36;
    constexpr int ASTR = NTR * RB;       // one A limb plane
    constexpr int ASZ  = 4 * ASTR;
    constexpr int BSTR = 64 * RB;        // one B (tap,limb) plane
    extern __shared__ int8_t smm[];

    const int tid = threadIdx.x;
    const int lane = tid & 31;
    const int wid = tid >> 5;
    const int warpm = wid & 3;
    const int warpn = (wid >> 2) & 3;
    const int g = lane >> 2;
    const int tq = lane & 3;
    const int t0  = blockIdx.x * 128;
    const int co0 = blockIdx.y * 64;
    const int bb  = blockIdx.z;
    const int GB  = STRIDE * t0 - 1;

    int   iacc0[2][2][4];   // class 0 exact
    int   iacc1[2][2][4];   // class 1 exact
    float accl[2][2][4];    // classes 2..4 merged
    #pragma unroll
    for (int mt = 0; mt < 2; ++mt)
        #pragma unroll
        for (int nt = 0; nt < 2; ++nt)
            #pragma unroll
            for (int q = 0; q < 4; ++q) {
                iacc0[mt][nt][q] = 0; iacc1[mt][nt][q] = 0; accl[mt][nt][q] = 0.f;
            }

    for (int cc = 0; cc < CIN / 32; ++cc) {
        __syncthreads();
        // ---- A: NTR rows x 32 int8 x 4 limbs ----
        for (int i = tid; i < NTR * 8; i += 512) {
            int r = i >> 3, u = i & 7;
            int grow = GB + r;
            bool ok = (grow >= 0 && grow < LIN);
            size_t bidx = ok ? ((((size_t)bb * LIN + grow) * CIN + cc * 32) >> 2) + u : 0;
            #pragma unroll
            for (int p = 0; p < 4; ++p) {
                uint32_t v = ok ? ((const uint32_t*)(Xq + p * xps))[bidx] : 0u;
                *(uint32_t*)&smm[p * ASTR + r * RB + u * 4] = v;
            }
        }
        // ---- B: all 3 taps x 64 co x 32 int8 x 4 limbs ----
        for (int i = tid; i < 3 * 64 * 8; i += 512) {
            int tap = i >> 9, rem = i & 511;
            int r = rem >> 3, u = rem & 7;
            size_t bidx = ((((size_t)tap * COUT + co0 + r) * CIN + cc * 32) >> 2) + u;
            #pragma unroll
            for (int p = 0; p < 4; ++p)
                *(uint32_t*)&smm[ASZ + (tap * 4 + p) * BSTR + r * RB + u * 4] =
                    ((const uint32_t*)(Wq + p * wps))[bidx];
        }
        __syncthreads();

        #pragma unroll
        for (int tap = 0; tap < 3; ++tap) {
            uint32_t af[4][2][4];
            #pragma unroll
            for (int mt = 0; mt < 2; ++mt) {
                int tl = warpm * 32 + mt * 16 + g;
                int ra = STRIDE * tl + tap;
                int ra8 = ra + 8 * STRIDE;
                #pragma unroll
                for (int p = 0; p < 4; ++p) {
                    const int8_t* base = &smm[p * ASTR];
                    af[p][mt][0] = *(const uint32_t*)&base[ra  * RB + tq * 4];
                    af[p][mt][1] = *(const uint32_t*)&base[ra8 * RB + tq * 4];
                    af[p][mt][2] = *(const uint32_t*)&base[ra  * RB + tq * 4 + 16];
                    af[p][mt][3] = *(const uint32_t*)&base[ra8 * RB + tq * 4 + 16];
                }
            }
            #pragma unroll
            for (int nt = 0; nt < 2; ++nt) {
                int rb = warpn * 16 + nt * 8 + g;
                uint32_t bf[4][2];
                #pragma unroll
                for (int p = 0; p < 4; ++p) {
                    const int8_t* base = &smm[ASZ + (tap * 4 + p) * BSTR];
                    bf[p][0] = *(const uint32_t*)&base[rb * RB + tq * 4];
                    bf[p][1] = *(const uint32_t*)&base[rb * RB + tq * 4 + 16];
                }
                // class 0 (exact int)
                mma_s8(iacc0[0][nt], af[0][0], bf[0][0], bf[0][1]);
                mma_s8(iacc0[1][nt], af[0][1], bf[0][0], bf[0][1]);
                // class 1 (exact int): (0,1),(1,0)
                mma_s8(iacc1[0][nt], af[0][0], bf[1][0], bf[1][1]);
                mma_s8(iacc1[0][nt], af[1][0], bf[0][0], bf[0][1]);
                mma_s8(iacc1[1][nt], af[0][1], bf[1][0], bf[1][1]);
                mma_s8(iacc1[1][nt], af[1][1], bf[0][0], bf[0][1]);
                // class 2: (0,2),(1,1),(2,0)  weight 2^-14
                {
                    int d0[4] = {0,0,0,0}, d1[4] = {0,0,0,0};
                    mma_s8(d0, af[0][0], bf[2][0], bf[2][1]);
                    mma_s8(d0, af[1][0], bf[1][0], bf[1][1]);
                    mma_s8(d0, af[2][0], bf[0][0], bf[0][1]);
                    mma_s8(d1, af[0][1], bf[2][0], bf[2][1]);
                    mma_s8(d1, af[1][1], bf[1][0], bf[1][1]);
                    mma_s8(d1, af[2][1], bf[0][0], bf[0][1]);
                    #pragma unroll
                    for (int q = 0; q < 4; ++q) {
                        accl[0][nt][q] = fmaf(__int2float_rn(d0[q]), 6.103515625e-05f, accl[0][nt][q]);
                        accl[1][nt][q] = fmaf(__int2float_rn(d1[q]), 6.103515625e-05f, accl[1][nt][q]);
                    }
                }
                // class 3: (0,3),(1,2),(2,1),(3,0)  weight 2^-21
                {
                    int d0[4] = {0,0,0,0}, d1[4] = {0,0,0,0};
                    mma_s8(d0, af[0][0], bf[3][0], bf[3][1]);
                    mma_s8(d0, af[1][0], bf[2][0], bf[2][1]);
                    mma_s8(d0, af[2][0], bf[1][0], bf[1][1]);
                    mma_s8(d0, af[3][0], bf[0][0], bf[0][1]);
                    mma_s8(d1, af[0][1], bf[3][0], bf[3][1]);
                    mma_s8(d1, af[1][1], bf[2][0], bf[2][1]);
                    mma_s8(d1, af[2][1], bf[1][0], bf[1][1]);
                    mma_s8(d1, af[3][1], bf[0][0], bf[0][1]);
                    #pragma unroll
                    for (int q = 0; q < 4; ++q) {
                        accl[0][nt][q] = fmaf(__int2float_rn(d0[q]), 4.76837158203125e-07f, accl[0][nt][q]);
                        accl[1][nt][q] = fmaf(__int2float_rn(d1[q]), 4.76837158203125e-07f, accl[1][nt][q]);
                    }
                }
                // class 4: (1,3),(2,2),(3,1)  weight 2^-28
                {
                    int d0[4] = {0,0,0,0}, d1[4] = {0,0,0,0};
                    mma_s8(d0, af[1][0], bf[3][0], bf[3][1]);
                    mma_s8(d0, af[2][0], bf[2][0], bf[2][1]);
                    mma_s8(d0, af[3][0], bf[1][0], bf[1][1]);
                    mma_s8(d1, af[1][1], bf[3][0], bf[3][1]);
                    mma_s8(d1, af[2][1], bf[2][0], bf[2][1]);
                    mma_s8(d1, af[3][1], bf[1][0], bf[1][1]);
                    #pragma unroll
                    for (int q = 0; q < 4; ++q) {
                        accl[0][nt][q] = fmaf(__int2float_rn(d0[q]), 3.7252902984619140625e-09f, accl[0][nt][q]);
                        accl[1][nt][q] = fmaf(__int2float_rn(d1[q]), 3.7252902984619140625e-09f, accl[1][nt][q]);
                    }
                }
            }
        }
    }

    // ---- epilogue ----
    #pragma unroll
    for (int nt = 0; nt < 2; ++nt) {
        int cog = co0 + warpn * 16 + nt * 8 + tq * 2;
        float b0 = __ldg(&bias[cog]);
        float b1 = __ldg(&bias[cog + 1]);
        #pragma unroll
        for (int mt = 0; mt < 2; ++mt) {
            #pragma unroll
            for (int half = 0; half < 2; ++half) {
                int t = t0 + warpm * 32 + mt * 16 + g + half * 8;
                float s0 = __int2float_rn(iacc0[mt][nt][half * 2])
                         + __int2float_rn(iacc1[mt][nt][half * 2]) * 0.0078125f
                         + accl[mt][nt][half * 2];
                float s1 = __int2float_rn(iacc0[mt][nt][half * 2 + 1])
                         + __int2float_rn(iacc1[mt][nt][half * 2 + 1]) * 0.0078125f
                         + accl[mt][nt][half * 2 + 1];
                float v0 = fmaf(s0, fscale, b0);
                float v1 = fmaf(s1, fscale, b1);
                if (RELU) {
                    v0 = (v0 >= 0.f) ? v0 : 0.01f * v0;
                    v1 = (v1 >= 0.f) ? v1 : 0.01f * v1;
                }
                if (SPLITOUT) {
                    signed char La[4], Lb[4];
                    enc_limbs(v0, invSo, La);
                    enc_limbs(v1, invSo, Lb);
                    size_t o = ((size_t)bb * LOUT + t) * COUT + cog;
                    #pragma unroll
                    for (int p = 0; p < 4; ++p) {
                        unsigned short pk = (unsigned short)((unsigned char)La[p]
                                          | ((unsigned short)(unsigned char)Lb[p] << 8));
                        *(unsigned short*)(Yq + p * yps + o) = pk;
                    }
                } else {
                    *(float2*)(Yf + ((size_t)bb * LOUT + t) * COUT + cog) = make_float2(v0, v1);
                }
            }
        }
    }
}

// ---------------- VQ splits (verified R3) ----------------
__global__ __launch_bounds__(256) void split_z_kernel(const float* __restrict__ zz)
{
    int idx = blockIdx.x * 256 + threadIdx.x;
    int row = idx >> 4, gs = idx & 15;
    const float* zr = zz + (size_t)row * C3 + gs * 8;
    float4 p0 = *(const float4*)zr;
    float4 p1 = *(const float4*)(zr + 4);
    float v[8] = {p0.x, p0.y, p0.z, p0.w, p1.x, p1.y, p1.z, p1.w};
    unsigned short h[8], l[8];
    #pragma unroll
    for (int e = 0; e < 8; ++e) bsplit2(v[e], h[e], l[e]);
    ((uint4*)g_zhi)[(size_t)row * 16 + gs] = pack8u(h);
    ((uint4*)g_zlo)[(size_t)row * 16 + gs] = pack8u(l);
    if (gs == 0) {
        const float* zf = zz + (size_t)row * C3;
        float a = 0.f;
        #pragma unroll 8
        for (int k = 0; k < C3; ++k) a = fmaf(zf[k], zf[k], a);
        g_arow[row] = a;
    }
}

__global__ __launch_bounds__(256) void split_e_kernel(const float* __restrict__ emb)
{
    int idx = blockIdx.x * 256 + threadIdx.x;
    int row = idx >> 4, gs = idx & 15;
    const float* er = emb + (size_t)row * C3 + gs * 8;
    float4 p0 = *(const float4*)er;
    float4 p1 = *(const float4*)(er + 4);
    float v[8] = {p0.x, p0.y, p0.z, p0.w, p1.x, p1.y, p1.z, p1.w};
    unsigned short h[8], l[8];
    #pragma unroll
    for (int e = 0; e < 8; ++e) bsplit2(v[e], h[e], l[e]);
    ((uint4*)g_ehi)[(size_t)row * 16 + gs] = pack8u(h);
    ((uint4*)g_elo)[(size_t)row * 16 + gs] = pack8u(l);
}

// ---------------- VQ on mma.sync (verified R3, unchanged) ----------------
#define ZH_OFF 0
#define ZL_OFF 34816
#define EH_OFF 69632
#define EL_OFF 87040
#define JF_OFF 104448
#define RV_OFF 104960
#define RJ_OFF 105984
#define VQ_DYN 107520
#define ROWPAD 272

__global__ __launch_bounds__(256, 1)
void vq_mma_kernel(const float* __restrict__ esq, const float* __restrict__ arow,
                   const float* __restrict__ emb,
                   float* __restrict__ codes, float* __restrict__ quant)
{
    extern __shared__ char smc[];
    const int tid = threadIdx.x;
    const int lane = tid & 31;
    const int wid = tid >> 5;
    const int warp_m = wid & 3;
    const int warp_n = wid >> 2;
    const int g = lane >> 2;
    const int tq = lane & 3;
    const int n0 = blockIdx.x * 128;
    const int mbase = warp_m * 32;

    for (int i = tid; i < 128 * 32; i += 256) {
        int row = i >> 5, u = i & 31;
        ((uint2*)(smc + ZH_OFF))[row * 34 + u] = ((const uint2*)g_zhi)[(size_t)(n0 + row) * 32 + u];
        ((uint2*)(smc + ZL_OFF))[row * 34 + u] = ((const uint2*)g_zlo)[(size_t)(n0 + row) * 32 + u];
    }

    float aval[4];
    #pragma unroll
    for (int s = 0; s < 4; ++s)
        aval[s] = __ldg(&arow[n0 + mbase + (s >> 1) * 16 + (s & 1) * 8 + g]);

    float best[4] = {3.4e38f, 3.4e38f, 3.4e38f, 3.4e38f};
    int   bj[4]   = {0, 0, 0, 0};

    for (int c = 0; c < 64; ++c) {
        __syncthreads();
        for (int i = tid; i < 64 * 32; i += 256) {
            int row = i >> 5, u = i & 31;
            ((uint2*)(smc + EH_OFF))[row * 34 + u] = ((const uint2*)g_ehi)[(size_t)(c * 64 + row) * 32 + u];
            ((uint2*)(smc + EL_OFF))[row * 34 + u] = ((const uint2*)g_elo)[(size_t)(c * 64 + row) * 32 + u];
        }
        __syncthreads();

        float acc[2][4][4];
        #pragma unroll
        for (int mt = 0; mt < 2; ++mt)
            #pragma unroll
            for (int nt = 0; nt < 4; ++nt)
                #pragma unroll
                for (int q = 0; q < 4; ++q) acc[mt][nt][q] = 0.f;

        #pragma unroll
        for (int ks = 0; ks < 8; ++ks) {
            const int k0 = ks * 16;
            uint32_t ah[2][4], al[2][4];
            #pragma unroll
            for (int mt = 0; mt < 2; ++mt) {
                int r0 = mbase + mt * 16 + g;
                int cb = (k0 + tq * 2) * 2;
                ah[mt][0] = *(const uint32_t*)(smc + ZH_OFF + r0 * ROWPAD + cb);
                ah[mt][1] = *(const uint32_t*)(smc + ZH_OFF + (r0 + 8) * ROWPAD + cb);
                ah[mt][2] = *(const uint32_t*)(smc + ZH_OFF + r0 * ROWPAD + cb + 16);
                ah[mt][3] = *(const uint32_t*)(smc + ZH_OFF + (r0 + 8) * ROWPAD + cb + 16);
                al[mt][0] = *(const uint32_t*)(smc + ZL_OFF + r0 * ROWPAD + cb);
                al[mt][1] = *(const uint32_t*)(smc + ZL_OFF + (r0 + 8) * ROWPAD + cb);
                al[mt][2] = *(const uint32_t*)(smc + ZL_OFF + r0 * ROWPAD + cb + 16);
                al[mt][3] = *(const uint32_t*)(smc + ZL_OFF + (r0 + 8) * ROWPAD + cb + 16);
            }
            #pragma unroll
            for (int nt = 0; nt < 4; ++nt) {
                int nrow = warp_n * 32 + nt * 8 + g;
                int cb = (k0 + tq * 2) * 2;
                uint32_t bh0 = *(const uint32_t*)(smc + EH_OFF + nrow * ROWPAD + cb);
                uint32_t bh1 = *(const uint32_t*)(smc + EH_OFF + nrow * ROWPAD + cb + 16);
                uint32_t bl0 = *(const uint32_t*)(smc + EL_OFF + nrow * ROWPAD + cb);
                uint32_t bl1 = *(const uint32_t*)(smc + EL_OFF + nrow * ROWPAD + cb + 16);
                #pragma unroll
                for (int mt = 0; mt < 2; ++mt) {
                    mma_bf16(acc[mt][nt], ah[mt], bh0, bh1);
                    mma_bf16(acc[mt][nt], ah[mt], bl0, bl1);
                    mma_bf16(acc[mt][nt], al[mt], bh0, bh1);
                }
            }
        }

        #pragma unroll
        for (int nt = 0; nt < 4; ++nt) {
            int jb = c * 64 + warp_n * 32 + nt * 8 + tq * 2;
            float e0 = __ldg(&esq[jb]);
            float e1 = __ldg(&esq[jb + 1]);
            #pragma unroll
            for (int mt = 0; mt < 2; ++mt) {
                int s0 = mt * 2, s1 = mt * 2 + 1;
                float d;
                d = (aval[s0] + e0) - 2.0f * acc[mt][nt][0];
                if (d < best[s0]) { best[s0] = d; bj[s0] = jb; }
                d = (aval[s0] + e1) - 2.0f * acc[mt][nt][1];
                if (d < best[s0]) { best[s0] = d; bj[s0] = jb + 1; }
                d = (aval[s1] + e0) - 2.0f * acc[mt][nt][2];
                if (d < best[s1]) { best[s1] = d; bj[s1] = jb; }
                d = (aval[s1] + e1) - 2.0f * acc[mt][nt][3];
                if (d < best[s1]) { best[s1] = d; bj[s1] = jb + 1; }
            }
        }
    }

    #pragma unroll
    for (int s = 0; s < 4; ++s) {
        #pragma unroll
        for (int off = 2; off >= 1; off >>= 1) {
            float ov = __shfl_xor_sync(0xffffffffu, best[s], off);
            int   oj = __shfl_xor_sync(0xffffffffu, bj[s],   off);
            if (ov < best[s] || (ov == best[s] && oj < bj[s])) { best[s] = ov; bj[s] = oj; }
        }
    }
    float* rv = (float*)(smc + RV_OFF);
    int*   rj = (int*)(smc + RJ_OFF);
    if (tq == 0) {
        #pragma unroll
        for (int s = 0; s < 4; ++s) {
            int row = mbase + (s >> 1) * 16 + (s & 1) * 8 + g;
            rv[row * 2 + warp_n] = best[s];
            rj[row * 2 + warp_n] = bj[s];
        }
    }
    __syncthreads();

    int* jf = (int*)(smc + JF_OFF);
    if (tid < 128) {
        float v0 = rv[tid * 2], v1 = rv[tid * 2 + 1];
        int   j0 = rj[tid * 2], j1 = rj[tid * 2 + 1];
        int j = (v1 < v0 || (v1 == v0 && j1 < j0)) ? j1 : j0;
        jf[tid] = j;
        codes[n0 + tid] = (float)j;
    }
    __syncthreads();

    for (int i = tid; i < 128 * 32; i += 256) {
        int row = i >> 5, q = i & 31;
        int j = jf[row];
        float4 v = __ldg((const float4*)emb + (size_t)j * 32 + q);
        ((float4*)quant)[(size_t)(n0 + row) * 32 + q] = v;
    }
}

// ---------------- host launch ----------------
static void* sym(const void* s) { void* p = nullptr; cudaGetSymbolAddress(&p, s); return p; }

#define C12_SMEM (4 * 258 * 36 + 12 * 64 * 36)   // 64800
#define C3_SMEM  (4 * 130 * 36 + 12 * 64 * 36)   // 46368

extern "C" void kernel_launch(void* const* d_in, const int* in_sizes, int n_in,
                              void* d_out, int out_size)
{
    const float* x       = (const float*)d_in[0];
    const float* conv1_w = (const float*)d_in[1];
    const float* conv1_b = (const float*)d_in[2];
    const float* bn1_g   = (const float*)d_in[3];
    const float* bn1_b   = (const float*)d_in[4];
    const float* bn1_m   = (const float*)d_in[5];
    const float* bn1_v   = (const float*)d_in[6];
    const float* conv2_w = (const float*)d_in[7];
    const float* conv2_b = (const float*)d_in[8];
    const float* bn2_g   = (const float*)d_in[9];
    const float* bn2_b   = (const float*)d_in[10];
    const float* bn2_m   = (const float*)d_in[11];
    const float* bn2_v   = (const float*)d_in[12];
    const float* conv3_w = (const float*)d_in[13];
    const float* conv3_b = (const float*)d_in[14];
    const float* emb     = (const float*)d_in[15];

    float* bb1 = (float*)sym(g_bb1);
    float* bb2 = (float*)sym(g_bb2);
    float* bb3 = (float*)sym(g_bb3);
    float* zz  = (float*)sym(g_zz);
    float* esq = (float*)sym(g_esq);
    float* arw = (float*)sym(g_arow);
    int8_t* xq  = (int8_t*)sym(g_xq);
    int8_t* h1q = (int8_t*)sym(g_h1q);
    int8_t* h2q = (int8_t*)sym(g_h2q);
    int8_t* w1q = (int8_t*)sym(g_w1q);
    int8_t* w2q = (int8_t*)sym(g_w2q);
    int8_t* w3q = (int8_t*)sym(g_w3q);

    float* out = (float*)d_out;
    float* codes_ptr;
    float* quant_ptr;
    const int FULL = NROWS + NROWS * C3;
    if (out_size >= FULL)            { codes_ptr = out; quant_ptr = out + NROWS; }
    else if (out_size == NROWS * C3) { codes_ptr = (float*)sym(g_dummy_codes); quant_ptr = out; }
    else if (out_size == NROWS)      { codes_ptr = out; quant_ptr = (float*)sym(g_dummy_q); }
    else                             { codes_ptr = out; quant_ptr = out + NROWS; }

    cudaFuncSetAttribute(vq_mma_kernel, cudaFuncAttributeMaxDynamicSharedMemorySize, VQ_DYN);
    cudaFuncSetAttribute((const void*)conv_imma2_kernel<C0, L0, L1, C1, 2, true, true>,
                         cudaFuncAttributeMaxDynamicSharedMemorySize, C12_SMEM);
    cudaFuncSetAttribute((const void*)conv_imma2_kernel<C1, L1, L2, C2, 2, true, true>,
                         cudaFuncAttributeMaxDynamicSharedMemorySize, C12_SMEM);
    cudaFuncSetAttribute((const void*)conv_imma2_kernel<C2, L2, L2, C3, 1, false, false>,
                         cudaFuncAttributeMaxDynamicSharedMemorySize, C3_SMEM);

    // prep: weights -> limb planes, VQ tables
    fold_enc_kernel<<<(3 * C1 * C0 + 255) / 256, 256>>>(conv1_w, conv1_b, bn1_g, bn1_b, bn1_m, bn1_v,
                                                        w1q, W1N, bb1, C0, C1);
    fold_enc_kernel<<<(3 * C2 * C1 + 255) / 256, 256>>>(conv2_w, conv2_b, bn2_g, bn2_b, bn2_m, bn2_v,
                                                        w2q, W2N, bb2, C1, C2);
    fold_enc_kernel<<<(3 * C3 * C2 + 255) / 256, 256>>>(conv3_w, conv3_b, nullptr, nullptr, nullptr, nullptr,
                                                        w3q, W3N, bb3, C2, C3);
    esq_kernel<<<(NCODES + 255) / 256, 256>>>(emb);
    split_e_kernel<<<(NCODES * 16) / 256, 256>>>(emb);

    // x -> transposed limb planes
    {
        dim3 gx(L0 / 32, C0 / 32, BATCH);
        xenc_kernel<<<gx, 256>>>(x, xq, XQN);
    }

    // encoder: exact int8 IMMA convs v2 (fused limb-encode outputs for conv1/2)
    {
        dim3 g1(L1 / 128, C1 / 64, BATCH);
        conv_imma2_kernel<C0, L0, L1, C1, 2, true, true><<<g1, 512, C12_SMEM>>>(
            xq, XQN, w1q, W1N, bb1, FSCALE1, INV_SH, h1q, H1N, nullptr);
    }
    {
        dim3 g2(L2 / 128, C2 / 64, BATCH);
        conv_imma2_kernel<C1, L1, L2, C2, 2, true, true><<<g2, 512, C12_SMEM>>>(
            h1q, H1N, w2q, W2N, bb2, FSCALE2, INV_SH, h2q, H2N, nullptr);
    }
    {
        dim3 g3(L2 / 128, C3 / 64, BATCH);
        conv_imma2_kernel<C2, L2, L2, C3, 1, false, false><<<g3, 512, C3_SMEM>>>(
            h2q, H2N, w3q, W3N, bb3, FSCALE3, 0.f, nullptr, 0, zz);
    }

    // VQ (proven path)
    split_z_kernel<<<(NROWS * 16) / 256, 256>>>(zz);
    vq_mma_kernel<<<NROWS / 128, 256, VQ_DYN>>>(esq, arw, emb, codes_ptr, quant_ptr);
}

// round 11
// speedup vs baseline: 1.8569x; 1.1426x over previous
#include <cuda_runtime.h>
#include <cuda_bf16.h>
#include <math.h>
#include <stdint.h>

// ---------------- problem constants ----------------
#define BATCH   32
#define L0      4096
#define L1      2048
#define L2      1024
#define C0      256
#define C1      256
#define C2      512
#define C3      128   // EMB_DIM
#define NCODES  4096
#define NROWS   (BATCH * L2)
#define BN_EPS  1e-5

// limb-plane element counts
#define XQN  ((size_t)BATCH * L0 * C0)
#define H1N  ((size_t)BATCH * L1 * C1)
#define H2N  ((size_t)BATCH * L2 * C2)
#define W1N  ((size_t)3 * C1 * C0)
#define W2N  ((size_t)3 * C2 * C1)
#define W3N  ((size_t)3 * C3 * C2)

// prescales (power-of-2, validated headroom R7-R10)
#define INV_SX 0.03125f     // S_x = 32
#define INV_SH 0.015625f    // S_h = 64
#define INV_SW 0.5f         // S_w = 2
// base-2^8 limbs: h = S_x*S_w*2^-16 * [C0 + C1*2^-8 + C2*2^-16 + C3*2^-24]
#define FSCALE1 0.0009765625f  // 32*2*2^-16 = 2^-10
#define FSCALE2 0.001953125f   // 64*2*2^-16 = 2^-9
#define FSCALE3 0.001953125f

// ---------------- device scratch ----------------
__device__ float g_bb1[C1];
__device__ float g_bb2[C2];
__device__ float g_bb3[C3];
__device__ float g_zz[(size_t)NROWS * C3];
__device__ float g_esq[NCODES];
__device__ float g_arow[NROWS];
__device__ float g_dummy_codes[NROWS];
__device__ float g_dummy_q[(size_t)NROWS * C3];
// int8 limb planes (limb i weight 2^-8(i+1))
__device__ int8_t g_xq[4 * XQN];
__device__ int8_t g_h1q[4 * H1N];
__device__ int8_t g_h2q[4 * H2N];
__device__ int8_t g_w1q[4 * W1N];
__device__ int8_t g_w2q[4 * W2N];
__device__ int8_t g_w3q[4 * W3N];
// VQ split operands (bf16x2, proven R3)
__device__ __nv_bfloat16 g_zhi[(size_t)NROWS * C3];
__device__ __nv_bfloat16 g_zlo[(size_t)NROWS * C3];
__device__ __nv_bfloat16 g_ehi[(size_t)NCODES * C3];
__device__ __nv_bfloat16 g_elo[(size_t)NCODES * C3];

// ---------------- helpers ----------------
__device__ __forceinline__ void bsplit2(float f, unsigned short& hi, unsigned short& lo)
{
    __nv_bfloat16 b0 = __float2bfloat16_rn(f);
    float r = f - __bfloat162float(b0);
    __nv_bfloat16 b1 = __float2bfloat16_rn(r);
    hi = __bfloat16_as_ushort(b0);
    lo = __bfloat16_as_ushort(b1);
}

__device__ __forceinline__ uint4 pack8u(const unsigned short* s)
{
    uint4 w;
    w.x = (uint32_t)s[0] | ((uint32_t)s[1] << 16);
    w.y = (uint32_t)s[2] | ((uint32_t)s[3] << 16);
    w.z = (uint32_t)s[4] | ((uint32_t)s[5] << 16);
    w.w = (uint32_t)s[6] | ((uint32_t)s[7] << 16);
    return w;
}

__device__ __forceinline__ void mma_bf16(float* c, const uint32_t* a, uint32_t b0, uint32_t b1)
{
    asm volatile(
        "mma.sync.aligned.m16n8k16.row.col.f32.bf16.bf16.f32 "
        "{%0,%1,%2,%3}, {%4,%5,%6,%7}, {%8,%9}, {%0,%1,%2,%3};"
        : "+f"(c[0]), "+f"(c[1]), "+f"(c[2]), "+f"(c[3])
        : "r"(a[0]), "r"(a[1]), "r"(a[2]), "r"(a[3]), "r"(b0), "r"(b1));
}

__device__ __forceinline__ void mma_s8(int* d, const uint32_t* a, uint32_t b0, uint32_t b1)
{
    asm volatile(
        "mma.sync.aligned.m16n8k32.row.col.s32.s8.s8.s32 "
        "{%0,%1,%2,%3}, {%4,%5,%6,%7}, {%8,%9}, {%0,%1,%2,%3};"
        : "+r"(d[0]), "+r"(d[1]), "+r"(d[2]), "+r"(d[3])
        : "r"(a[0]), "r"(a[1]), "r"(a[2]), "r"(a[3]), "r"(b0), "r"(b1));
}

// 4-limb balanced base-2^8 decomposition (exact): u = sum_i L[i]*2^{-8(i+1)} + eps, |eps|<=2^-33
// limbs in [-128,127]; top limb |L0| <= ~60 for |u| <= 0.24.
__device__ __forceinline__ void enc8(float v, float invS, signed char* L)
{
    float u = v * invS;
    float mhf = rintf(u * 65536.f);
    float r = fmaf(mhf, -1.52587890625e-05f, u);     // exact residual, |r| <= 2^-17
    int ml = (int)rintf(r * 4294967296.f);           // |ml| <= 2^15
    int mh = (int)mhf;                               // |mh| <= 2^14-ish
    int d0 = ((ml + 128) & 255) - 128;  ml = (ml - d0) >> 8;     // |ml| <= 129
    int d1 = ((ml + 128) & 255) - 128;  mh += (ml - d1) >> 8;    // carry in {-1,0,1}
    int d2 = ((mh + 128) & 255) - 128;  mh = (mh - d2) >> 8;     // |mh| <= ~60
    L[0] = (signed char)mh;   // weight 2^-8
    L[1] = (signed char)d2;   // weight 2^-16
    L[2] = (signed char)d1;   // weight 2^-24
    L[3] = (signed char)d0;   // weight 2^-32
}

// ---------------- prep kernels ----------------
__global__ void fold_enc_kernel(const float* __restrict__ w, const float* __restrict__ bias,
                                const float* __restrict__ g, const float* __restrict__ be,
                                const float* __restrict__ m, const float* __restrict__ v,
                                int8_t* __restrict__ wq, size_t wps,
                                float* __restrict__ bout, int CIN, int COUT)
{
    int idx = blockIdx.x * 256 + threadIdx.x;
    int total = 3 * COUT * CIN;
    if (idx < total) {
        int tap = idx / (COUT * CIN);
        int rem = idx - tap * COUT * CIN;
        int co = rem / CIN;
        int ci = rem - co * CIN;
        float scale = 1.0f;
        if (g) {
            double dinv = (double)g[co] / sqrt((double)v[co] + (double)BN_EPS);
            scale = (float)dinv;
        }
        float val = w[((size_t)co * CIN + ci) * 3 + tap] * scale;
        signed char L[4];
        enc8(val, INV_SW, L);
        #pragma unroll
        for (int p = 0; p < 4; ++p) wq[p * wps + idx] = L[p];
    }
    if (idx < COUT) {
        float bo;
        if (g) {
            double dinv = (double)g[idx] / sqrt((double)v[idx] + (double)BN_EPS);
            bo = (float)((double)bias[idx] * dinv + (double)be[idx] - (double)m[idx] * dinv);
        } else {
            bo = bias[idx];
        }
        bout[idx] = bo;
    }
}

__global__ void esq_kernel(const float* __restrict__ emb)
{
    int j = blockIdx.x * 256 + threadIdx.x;
    if (j < NCODES) {
        const float* e = emb + (size_t)j * C3;
        float s = 0.f;
        #pragma unroll 8
        for (int k = 0; k < C3; ++k) s = fmaf(e[k], e[k], s);
        g_esq[j] = s;
    }
}

// x [b][256][4096] fp32 -> 4 limb planes [b][4096][256] int8 (transpose + encode)
__global__ __launch_bounds__(256) void xenc_kernel(const float* __restrict__ x,
                                                   int8_t* __restrict__ q, size_t qps)
{
    __shared__ float tile[32][33];
    int b = blockIdx.z, t0 = blockIdx.x * 32, c0 = blockIdx.y * 32;
    int tx = threadIdx.x & 31, ty = threadIdx.x >> 5;
    #pragma unroll
    for (int i = 0; i < 4; ++i)
        tile[ty + 8 * i][tx] = x[((size_t)b * C0 + c0 + ty + 8 * i) * L0 + t0 + tx];
    __syncthreads();
    int tl = threadIdx.x & 31;
    int c4 = threadIdx.x >> 5;
    signed char L[4][4];
    #pragma unroll
    for (int k = 0; k < 4; ++k) {
        signed char tmp[4];
        enc8(tile[c4 * 4 + k][tl], INV_SX, tmp);
        #pragma unroll
        for (int p = 0; p < 4; ++p) L[p][k] = tmp[p];
    }
    size_t o = ((size_t)b * L0 + t0 + tl) * C0 + c0 + c4 * 4;
    #pragma unroll
    for (int p = 0; p < 4; ++p)
        *(char4*)(q + p * qps + o) = make_char4(L[p][0], L[p][1], L[p][2], L[p][3]);
}

// ---------------- conv via exact int8 IMMA v3 (base-2^8 limbs) ----------------
// 512 threads / 16 warps (4 warpm x 4 warpn), CTA 128t x 64co, warp m32 x n16.
// Classes 0..3 ALL persistent int32 (no mainloop scalar); class 4+ dropped (~4e-8 rel).
// Epilogue: s = C0 + C1*2^-8 + C2*2^-16 + C3*2^-24; y = s*FSCALE + bias.
template<int CIN, int LIN, int LOUT, int COUT, int STRIDE, bool RELU, bool SPLITOUT>
__global__ __launch_bounds__(512, 1)
void conv_imma3_kernel(const int8_t* __restrict__ Xq, size_t xps,
                       const int8_t* __restrict__ Wq, size_t wps,
                       const float* __restrict__ bias, float fscale, float invSo,
                       int8_t* __restrict__ Yq, size_t yps,
                       float* __restrict__ Yf)
{
    constexpr int NTR = STRIDE * 128 + 2;
    constexpr int RB = 36;
    constexpr int ASTR = NTR * RB;
    constexpr int ASZ  = 4 * ASTR;
    constexpr int BSTR = 64 * RB;
    extern __shared__ int8_t smm[];

    const int tid = threadIdx.x;
    const int lane = tid & 31;
    const int wid = tid >> 5;
    const int warpm = wid & 3;
    const int warpn = (wid >> 2) & 3;
    const int g = lane >> 2;
    const int tq = lane & 3;
    const int t0  = blockIdx.x * 128;
    const int co0 = blockIdx.y * 64;
    const int bb  = blockIdx.z;
    const int GB  = STRIDE * t0 - 1;

    int ia0[2][2][4], ia1[2][2][4], ia2[2][2][4], ia3[2][2][4];
    #pragma unroll
    for (int mt = 0; mt < 2; ++mt)
        #pragma unroll
        for (int nt = 0; nt < 2; ++nt)
            #pragma unroll
            for (int q = 0; q < 4; ++q) {
                ia0[mt][nt][q] = 0; ia1[mt][nt][q] = 0;
                ia2[mt][nt][q] = 0; ia3[mt][nt][q] = 0;
            }

    for (int cc = 0; cc < CIN / 32; ++cc) {
        __syncthreads();
        // ---- A: NTR rows x 32 int8 x 4 limbs ----
        for (int i = tid; i < NTR * 8; i += 512) {
            int r = i >> 3, u = i & 7;
            int grow = GB + r;
            bool ok = (grow >= 0 && grow < LIN);
            size_t bidx = ok ? ((((size_t)bb * LIN + grow) * CIN + cc * 32) >> 2) + u : 0;
            #pragma unroll
            for (int p = 0; p < 4; ++p) {
                uint32_t v = ok ? ((const uint32_t*)(Xq + p * xps))[bidx] : 0u;
                *(uint32_t*)&smm[p * ASTR + r * RB + u * 4] = v;
            }
        }
        // ---- B: 3 taps x 64 co x 32 int8 x 4 limbs ----
        for (int i = tid; i < 3 * 64 * 8; i += 512) {
            int tap = i >> 9, rem = i & 511;
            int r = rem >> 3, u = rem & 7;
            size_t bidx = ((((size_t)tap * COUT + co0 + r) * CIN + cc * 32) >> 2) + u;
            #pragma unroll
            for (int p = 0; p < 4; ++p)
                *(uint32_t*)&smm[ASZ + (tap * 4 + p) * BSTR + r * RB + u * 4] =
                    ((const uint32_t*)(Wq + p * wps))[bidx];
        }
        __syncthreads();

        #pragma unroll
        for (int tap = 0; tap < 3; ++tap) {
            uint32_t af[4][2][4];
            #pragma unroll
            for (int mt = 0; mt < 2; ++mt) {
                int tl = warpm * 32 + mt * 16 + g;
                int ra = STRIDE * tl + tap;
                int ra8 = ra + 8 * STRIDE;
                #pragma unroll
                for (int p = 0; p < 4; ++p) {
                    const int8_t* base = &smm[p * ASTR];
                    af[p][mt][0] = *(const uint32_t*)&base[ra  * RB + tq * 4];
                    af[p][mt][1] = *(const uint32_t*)&base[ra8 * RB + tq * 4];
                    af[p][mt][2] = *(const uint32_t*)&base[ra  * RB + tq * 4 + 16];
                    af[p][mt][3] = *(const uint32_t*)&base[ra8 * RB + tq * 4 + 16];
                }
            }
            #pragma unroll
            for (int nt = 0; nt < 2; ++nt) {
                int rb = warpn * 16 + nt * 8 + g;
                uint32_t bf[4][2];
                #pragma unroll
                for (int p = 0; p < 4; ++p) {
                    const int8_t* base = &smm[ASZ + (tap * 4 + p) * BSTR];
                    bf[p][0] = *(const uint32_t*)&base[rb * RB + tq * 4];
                    bf[p][1] = *(const uint32_t*)&base[rb * RB + tq * 4 + 16];
                }
                // class 0: (0,0)
                mma_s8(ia0[0][nt], af[0][0], bf[0][0], bf[0][1]);
                mma_s8(ia0[1][nt], af[0][1], bf[0][0], bf[0][1]);
                // class 1: (0,1),(1,0)
                mma_s8(ia1[0][nt], af[0][0], bf[1][0], bf[1][1]);
                mma_s8(ia1[0][nt], af[1][0], bf[0][0], bf[0][1]);
                mma_s8(ia1[1][nt], af[0][1], bf[1][0], bf[1][1]);
                mma_s8(ia1[1][nt], af[1][1], bf[0][0], bf[0][1]);
                // class 2: (0,2),(1,1),(2,0)
                mma_s8(ia2[0][nt], af[0][0], bf[2][0], bf[2][1]);
                mma_s8(ia2[0][nt], af[1][0], bf[1][0], bf[1][1]);
                mma_s8(ia2[0][nt], af[2][0], bf[0][0], bf[0][1]);
                mma_s8(ia2[1][nt], af[0][1], bf[2][0], bf[2][1]);
                mma_s8(ia2[1][nt], af[1][1], bf[1][0], bf[1][1]);
                mma_s8(ia2[1][nt], af[2][1], bf[0][0], bf[0][1]);
                // class 3: (0,3),(1,2),(2,1),(3,0)
                mma_s8(ia3[0][nt], af[0][0], bf[3][0], bf[3][1]);
                mma_s8(ia3[0][nt], af[1][0], bf[2][0], bf[2][1]);
                mma_s8(ia3[0][nt], af[2][0], bf[1][0], bf[1][1]);
                mma_s8(ia3[0][nt], af[3][0], bf[0][0], bf[0][1]);
                mma_s8(ia3[1][nt], af[0][1], bf[3][0], bf[3][1]);
                mma_s8(ia3[1][nt], af[1][1], bf[2][0], bf[2][1]);
                mma_s8(ia3[1][nt], af[2][1], bf[1][0], bf[1][1]);
                mma_s8(ia3[1][nt], af[3][1], bf[0][0], bf[0][1]);
            }
        }
    }

    // ---- epilogue: single combine per output ----
    #pragma unroll
    for (int nt = 0; nt < 2; ++nt) {
        int cog = co0 + warpn * 16 + nt * 8 + tq * 2;
        float b0 = __ldg(&bias[cog]);
        float b1 = __ldg(&bias[cog + 1]);
        #pragma unroll
        for (int mt = 0; mt < 2; ++mt) {
            #pragma unroll
            for (int half = 0; half < 2; ++half) {
                int t = t0 + warpm * 32 + mt * 16 + g + half * 8;
                int q0 = half * 2, q1 = half * 2 + 1;
                float s0 = __int2float_rn(ia0[mt][nt][q0])
                         + __int2float_rn(ia1[mt][nt][q0]) * 0.00390625f
                         + __int2float_rn(ia2[mt][nt][q0]) * 1.52587890625e-05f
                         + __int2float_rn(ia3[mt][nt][q0]) * 5.9604644775390625e-08f;
                float s1 = __int2float_rn(ia0[mt][nt][q1])
                         + __int2float_rn(ia1[mt][nt][q1]) * 0.00390625f
                         + __int2float_rn(ia2[mt][nt][q1]) * 1.52587890625e-05f
                         + __int2float_rn(ia3[mt][nt][q1]) * 5.9604644775390625e-08f;
                float v0 = fmaf(s0, fscale, b0);
                float v1 = fmaf(s1, fscale, b1);
                if (RELU) {
                    v0 = (v0 >= 0.f) ? v0 : 0.01f * v0;
                    v1 = (v1 >= 0.f) ? v1 : 0.01f * v1;
                }
                if (SPLITOUT) {
                    signed char La[4], Lb[4];
                    enc8(v0, invSo, La);
                    enc8(v1, invSo, Lb);
                    size_t o = ((size_t)bb * LOUT + t) * COUT + cog;
                    #pragma unroll
                    for (int p = 0; p < 4; ++p) {
                        unsigned short pk = (unsigned short)((unsigned char)La[p]
                                          | ((unsigned short)(unsigned char)Lb[p] << 8));
                        *(unsigned short*)(Yq + p * yps + o) = pk;
                    }
                } else {
                    *(float2*)(Yf + ((size_t)bb * LOUT + t) * COUT + cog) = make_float2(v0, v1);
                }
            }
        }
    }
}

// ---------------- VQ splits (verified R3) ----------------
__global__ __launch_bounds__(256) void split_z_kernel(const float* __restrict__ zz)
{
    int idx = blockIdx.x * 256 + threadIdx.x;
    int row = idx >> 4, gs = idx & 15;
    const float* zr = zz + (size_t)row * C3 + gs * 8;
    float4 p0 = *(const float4*)zr;
    float4 p1 = *(const float4*)(zr + 4);
    float v[8] = {p0.x, p0.y, p0.z, p0.w, p1.x, p1.y, p1.z, p1.w};
    unsigned short h[8], l[8];
    #pragma unroll
    for (int e = 0; e < 8; ++e) bsplit2(v[e], h[e], l[e]);
    ((uint4*)g_zhi)[(size_t)row * 16 + gs] = pack8u(h);
    ((uint4*)g_zlo)[(size_t)row * 16 + gs] = pack8u(l);
    if (gs == 0) {
        const float* zf = zz + (size_t)row * C3;
        float a = 0.f;
        #pragma unroll 8
        for (int k = 0; k < C3; ++k) a = fmaf(zf[k], zf[k], a);
        g_arow[row] = a;
    }
}

__global__ __launch_bounds__(256) void split_e_kernel(const float* __restrict__ emb)
{
    int idx = blockIdx.x * 256 + threadIdx.x;
    int row = idx >> 4, gs = idx & 15;
    const float* er = emb + (size_t)row * C3 + gs * 8;
    float4 p0 = *(const float4*)er;
    float4 p1 = *(const float4*)(er + 4);
    float v[8] = {p0.x, p0.y, p0.z, p0.w, p1.x, p1.y, p1.z, p1.w};
    unsigned short h[8], l[8];
    #pragma unroll
    for (int e = 0; e < 8; ++e) bsplit2(v[e], h[e], l[e]);
    ((uint4*)g_ehi)[(size_t)row * 16 + gs] = pack8u(h);
    ((uint4*)g_elo)[(size_t)row * 16 + gs] = pack8u(l);
}

// ---------------- VQ on mma.sync (verified R3, unchanged) ----------------
#define ZH_OFF 0
#define ZL_OFF 34816
#define EH_OFF 69632
#define EL_OFF 87040
#define JF_OFF 104448
#define RV_OFF 104960
#define RJ_OFF 105984
#define VQ_DYN 107520
#define ROWPAD 272

__global__ __launch_bounds__(256, 1)
void vq_mma_kernel(const float* __restrict__ esq, const float* __restrict__ arow,
                   const float* __restrict__ emb,
                   float* __restrict__ codes, float* __restrict__ quant)
{
    extern __shared__ char smc[];
    const int tid = threadIdx.x;
    const int lane = tid & 31;
    const int wid = tid >> 5;
    const int warp_m = wid & 3;
    const int warp_n = wid >> 2;
    const int g = lane >> 2;
    const int tq = lane & 3;
    const int n0 = blockIdx.x * 128;
    const int mbase = warp_m * 32;

    for (int i = tid; i < 128 * 32; i += 256) {
        int row = i >> 5, u = i & 31;
        ((uint2*)(smc + ZH_OFF))[row * 34 + u] = ((const uint2*)g_zhi)[(size_t)(n0 + row) * 32 + u];
        ((uint2*)(smc + ZL_OFF))[row * 34 + u] = ((const uint2*)g_zlo)[(size_t)(n0 + row) * 32 + u];
    }

    float aval[4];
    #pragma unroll
    for (int s = 0; s < 4; ++s)
        aval[s] = __ldg(&arow[n0 + mbase + (s >> 1) * 16 + (s & 1) * 8 + g]);

    float best[4] = {3.4e38f, 3.4e38f, 3.4e38f, 3.4e38f};
    int   bj[4]   = {0, 0, 0, 0};

    for (int c = 0; c < 64; ++c) {
        __syncthreads();
        for (int i = tid; i < 64 * 32; i += 256) {
            int row = i >> 5, u = i & 31;
            ((uint2*)(smc + EH_OFF))[row * 34 + u] = ((const uint2*)g_ehi)[(size_t)(c * 64 + row) * 32 + u];
            ((uint2*)(smc + EL_OFF))[row * 34 + u] = ((const uint2*)g_elo)[(size_t)(c * 64 + row) * 32 + u];
        }
        __syncthreads();

        float acc[2][4][4];
        #pragma unroll
        for (int mt = 0; mt < 2; ++mt)
            #pragma unroll
            for (int nt = 0; nt < 4; ++nt)
                #pragma unroll
                for (int q = 0; q < 4; ++q) acc[mt][nt][q] = 0.f;

        #pragma unroll
        for (int ks = 0; ks < 8; ++ks) {
            const int k0 = ks * 16;
            uint32_t ah[2][4], al[2][4];
            #pragma unroll
            for (int mt = 0; mt < 2; ++mt) {
                int r0 = mbase + mt * 16 + g;
                int cb = (k0 + tq * 2) * 2;
                ah[mt][0] = *(const uint32_t*)(smc + ZH_OFF + r0 * ROWPAD + cb);
                ah[mt][1] = *(const uint32_t*)(smc + ZH_OFF + (r0 + 8) * ROWPAD + cb);
                ah[mt][2] = *(const uint32_t*)(smc + ZH_OFF + r0 * ROWPAD + cb + 16);
                ah[mt][3] = *(const uint32_t*)(smc + ZH_OFF + (r0 + 8) * ROWPAD + cb + 16);
                al[mt][0] = *(const uint32_t*)(smc + ZL_OFF + r0 * ROWPAD + cb);
                al[mt][1] = *(const uint32_t*)(smc + ZL_OFF + (r0 + 8) * ROWPAD + cb);
                al[mt][2] = *(const uint32_t*)(smc + ZL_OFF + r0 * ROWPAD + cb + 16);
                al[mt][3] = *(const uint32_t*)(smc + ZL_OFF + (r0 + 8) * ROWPAD + cb + 16);
            }
            #pragma unroll
            for (int nt = 0; nt < 4; ++nt) {
                int nrow = warp_n * 32 + nt * 8 + g;
                int cb = (k0 + tq * 2) * 2;
                uint32_t bh0 = *(const uint32_t*)(smc + EH_OFF + nrow * ROWPAD + cb);
                uint32_t bh1 = *(const uint32_t*)(smc + EH_OFF + nrow * ROWPAD + cb + 16);
                uint32_t bl0 = *(const uint32_t*)(smc + EL_OFF + nrow * ROWPAD + cb);
                uint32_t bl1 = *(const uint32_t*)(smc + EL_OFF + nrow * ROWPAD + cb + 16);
                #pragma unroll
                for (int mt = 0; mt < 2; ++mt) {
                    mma_bf16(acc[mt][nt], ah[mt], bh0, bh1);
                    mma_bf16(acc[mt][nt], ah[mt], bl0, bl1);
                    mma_bf16(acc[mt][nt], al[mt], bh0, bh1);
                }
            }
        }

        #pragma unroll
        for (int nt = 0; nt < 4; ++nt) {
            int jb = c * 64 + warp_n * 32 + nt * 8 + tq * 2;
            float e0 = __ldg(&esq[jb]);
            float e1 = __ldg(&esq[jb + 1]);
            #pragma unroll
            for (int mt = 0; mt < 2; ++mt) {
                int s0 = mt * 2, s1 = mt * 2 + 1;
                float d;
                d = (aval[s0] + e0) - 2.0f * acc[mt][nt][0];
                if (d < best[s0]) { best[s0] = d; bj[s0] = jb; }
                d = (aval[s0] + e1) - 2.0f * acc[mt][nt][1];
                if (d < best[s0]) { best[s0] = d; bj[s0] = jb + 1; }
                d = (aval[s1] + e0) - 2.0f * acc[mt][nt][2];
                if (d < best[s1]) { best[s1] = d; bj[s1] = jb; }
                d = (aval[s1] + e1) - 2.0f * acc[mt][nt][3];
                if (d < best[s1]) { best[s1] = d; bj[s1] = jb + 1; }
            }
        }
    }

    #pragma unroll
    for (int s = 0; s < 4; ++s) {
        #pragma unroll
        for (int off = 2; off >= 1; off >>= 1) {
            float ov = __shfl_xor_sync(0xffffffffu, best[s], off);
            int   oj = __shfl_xor_sync(0xffffffffu, bj[s],   off);
            if (ov < best[s] || (ov == best[s] && oj < bj[s])) { best[s] = ov; bj[s] = oj; }
        }
    }
    float* rv = (float*)(smc + RV_OFF);
    int*   rj = (int*)(smc + RJ_OFF);
    if (tq == 0) {
        #pragma unroll
        for (int s = 0; s < 4; ++s) {
            int row = mbase + (s >> 1) * 16 + (s & 1) * 8 + g;
            rv[row * 2 + warp_n] = best[s];
            rj[row * 2 + warp_n] = bj[s];
        }
    }
    __syncthreads();

    int* jf = (int*)(smc + JF_OFF);
    if (tid < 128) {
        float v0 = rv[tid * 2], v1 = rv[tid * 2 + 1];
        int   j0 = rj[tid * 2], j1 = rj[tid * 2 + 1];
        int j = (v1 < v0 || (v1 == v0 && j1 < j0)) ? j1 : j0;
        jf[tid] = j;
        codes[n0 + tid] = (float)j;
    }
    __syncthreads();

    for (int i = tid; i < 128 * 32; i += 256) {
        int row = i >> 5, q = i & 31;
        int j = jf[row];
        float4 v = __ldg((const float4*)emb + (size_t)j * 32 + q);
        ((float4*)quant)[(size_t)(n0 + row) * 32 + q] = v;
    }
}

// ---------------- host launch ----------------
static void* sym(const void* s) { void* p = nullptr; cudaGetSymbolAddress(&p, s); return p; }

#define C12_SMEM (4 * 258 * 36 + 12 * 64 * 36)   // 64800
#define C3_SMEM  (4 * 130 * 36 + 12 * 64 * 36)   // 46368

extern "C" void kernel_launch(void* const* d_in, const int* in_sizes, int n_in,
                              void* d_out, int out_size)
{
    const float* x       = (const float*)d_in[0];
    const float* conv1_w = (const float*)d_in[1];
    const float* conv1_b = (const float*)d_in[2];
    const float* bn1_g   = (const float*)d_in[3];
    const float* bn1_b   = (const float*)d_in[4];
    const float* bn1_m   = (const float*)d_in[5];
    const float* bn1_v   = (const float*)d_in[6];
    const float* conv2_w = (const float*)d_in[7];
    const float* conv2_b = (const float*)d_in[8];
    const float* bn2_g   = (const float*)d_in[9];
    const float* bn2_b   = (const float*)d_in[10];
    const float* bn2_m   = (const float*)d_in[11];
    const float* bn2_v   = (const float*)d_in[12];
    const float* conv3_w = (const float*)d_in[13];
    const float* conv3_b = (const float*)d_in[14];
    const float* emb     = (const float*)d_in[15];

    float* bb1 = (float*)sym(g_bb1);
    float* bb2 = (float*)sym(g_bb2);
    float* bb3 = (float*)sym(g_bb3);
    float* zz  = (float*)sym(g_zz);
    float* esq = (float*)sym(g_esq);
    float* arw = (float*)sym(g_arow);
    int8_t* xq  = (int8_t*)sym(g_xq);
    int8_t* h1q = (int8_t*)sym(g_h1q);
    int8_t* h2q = (int8_t*)sym(g_h2q);
    int8_t* w1q = (int8_t*)sym(g_w1q);
    int8_t* w2q = (int8_t*)sym(g_w2q);
    int8_t* w3q = (int8_t*)sym(g_w3q);

    float* out = (float*)d_out;
    float* codes_ptr;
    float* quant_ptr;
    const int FULL = NROWS + NROWS * C3;
    if (out_size >= FULL)            { codes_ptr = out; quant_ptr = out + NROWS; }
    else if (out_size == NROWS * C3) { codes_ptr = (float*)sym(g_dummy_codes); quant_ptr = out; }
    else if (out_size == NROWS)      { codes_ptr = out; quant_ptr = (float*)sym(g_dummy_q); }
    else                             { codes_ptr = out; quant_ptr = out + NROWS; }

    cudaFuncSetAttribute(vq_mma_kernel, cudaFuncAttributeMaxDynamicSharedMemorySize, VQ_DYN);
    cudaFuncSetAttribute((const void*)conv_imma3_kernel<C0, L0, L1, C1, 2, true, true>,
                         cudaFuncAttributeMaxDynamicSharedMemorySize, C12_SMEM);
    cudaFuncSetAttribute((const void*)conv_imma3_kernel<C1, L1, L2, C2, 2, true, true>,
                         cudaFuncAttributeMaxDynamicSharedMemorySize, C12_SMEM);
    cudaFuncSetAttribute((const void*)conv_imma3_kernel<C2, L2, L2, C3, 1, false, false>,
                         cudaFuncAttributeMaxDynamicSharedMemorySize, C3_SMEM);

    // prep: weights -> limb planes, VQ tables
    fold_enc_kernel<<<(3 * C1 * C0 + 255) / 256, 256>>>(conv1_w, conv1_b, bn1_g, bn1_b, bn1_m, bn1_v,
                                                        w1q, W1N, bb1, C0, C1);
    fold_enc_kernel<<<(3 * C2 * C1 + 255) / 256, 256>>>(conv2_w, conv2_b, bn2_g, bn2_b, bn2_m, bn2_v,
                                                        w2q, W2N, bb2, C1, C2);
    fold_enc_kernel<<<(3 * C3 * C2 + 255) / 256, 256>>>(conv3_w, conv3_b, nullptr, nullptr, nullptr, nullptr,
                                                        w3q, W3N, bb3, C2, C3);
    esq_kernel<<<(NCODES + 255) / 256, 256>>>(emb);
    split_e_kernel<<<(NCODES * 16) / 256, 256>>>(emb);

    // x -> transposed limb planes
    {
        dim3 gx(L0 / 32, C0 / 32, BATCH);
        xenc_kernel<<<gx, 256>>>(x, xq, XQN);
    }

    // encoder: exact int8 IMMA convs v3 (fused limb-encode outputs for conv1/2)
    {
        dim3 g1(L1 / 128, C1 / 64, BATCH);
        conv_imma3_kernel<C0, L0, L1, C1, 2, true, true><<<g1, 512, C12_SMEM>>>(
            xq, XQN, w1q, W1N, bb1, FSCALE1, INV_SH, h1q, H1N, nullptr);
    }
    {
        dim3 g2(L2 / 128, C2 / 64, BATCH);
        conv_imma3_kernel<C1, L1, L2, C2, 2, true, true><<<g2, 512, C12_SMEM>>>(
            h1q, H1N, w2q, W2N, bb2, FSCALE2, INV_SH, h2q, H2N, nullptr);
    }
    {
        dim3 g3(L2 / 128, C3 / 64, BATCH);
        conv_imma3_kernel<C2, L2, L2, C3, 1, false, false><<<g3, 512, C3_SMEM>>>(
            h2q, H2N, w3q, W3N, bb3, FSCALE3, 0.f, nullptr, 0, zz);
    }

    // VQ (proven path)
    split_z_kernel<<<(NROWS * 16) / 256, 256>>>(zz);
    vq_mma_kernel<<<NROWS / 128, 256, VQ_DYN>>>(esq, arw, emb, codes_ptr, quant_ptr);
}

// round 12
// speedup vs baseline: 2.2166x; 1.1937x over previous
#include <cuda_runtime.h>
#include <cuda_bf16.h>
#include <math.h>
#include <stdint.h>

// ---------------- problem constants ----------------
#define BATCH   32
#define L0      4096
#define L1      2048
#define L2      1024
#define C0      256
#define C1      256
#define C2      512
#define C3      128   // EMB_DIM
#define NCODES  4096
#define NROWS   (BATCH * L2)
#define BN_EPS  1e-5

// limb-plane element counts
#define XQN  ((size_t)BATCH * L0 * C0)
#define H1N  ((size_t)BATCH * L1 * C1)
#define H2N  ((size_t)BATCH * L2 * C2)
#define W1N  ((size_t)3 * C1 * C0)
#define W2N  ((size_t)3 * C2 * C1)
#define W3N  ((size_t)3 * C3 * C2)

// prescales (power-of-2, validated headroom R7-R11)
#define INV_SX 0.03125f     // S_x = 32
#define INV_SH 0.015625f    // S_h = 64
#define INV_SW 0.5f         // S_w = 2
#define FSCALE1 0.0009765625f  // 32*2*2^-16
#define FSCALE2 0.001953125f   // 64*2*2^-16
#define FSCALE3 0.001953125f

// ---------------- device scratch ----------------
__device__ float g_bb1[C1];
__device__ float g_bb2[C2];
__device__ float g_bb3[C3];
__device__ float g_zz[(size_t)NROWS * C3];
__device__ float g_esq[NCODES];
__device__ float g_arow[NROWS];
__device__ float g_dummy_codes[NROWS];
__device__ float g_dummy_q[(size_t)NROWS * C3];
__device__ int8_t g_xq[4 * XQN];
__device__ int8_t g_h1q[4 * H1N];
__device__ int8_t g_h2q[4 * H2N];
__device__ int8_t g_w1q[4 * W1N];
__device__ int8_t g_w2q[4 * W2N];
__device__ int8_t g_w3q[4 * W3N];
__device__ __nv_bfloat16 g_zhi[(size_t)NROWS * C3];
__device__ __nv_bfloat16 g_zlo[(size_t)NROWS * C3];
__device__ __nv_bfloat16 g_ehi[(size_t)NCODES * C3];
__device__ __nv_bfloat16 g_elo[(size_t)NCODES * C3];

// ---------------- helpers ----------------
__device__ __forceinline__ void bsplit2(float f, unsigned short& hi, unsigned short& lo)
{
    __nv_bfloat16 b0 = __float2bfloat16_rn(f);
    float r = f - __bfloat162float(b0);
    __nv_bfloat16 b1 = __float2bfloat16_rn(r);
    hi = __bfloat16_as_ushort(b0);
    lo = __bfloat16_as_ushort(b1);
}

__device__ __forceinline__ uint4 pack8u(const unsigned short* s)
{
    uint4 w;
    w.x = (uint32_t)s[0] | ((uint32_t)s[1] << 16);
    w.y = (uint32_t)s[2] | ((uint32_t)s[3] << 16);
    w.z = (uint32_t)s[4] | ((uint32_t)s[5] << 16);
    w.w = (uint32_t)s[6] | ((uint32_t)s[7] << 16);
    return w;
}

__device__ __forceinline__ void mma_bf16(float* c, const uint32_t* a, uint32_t b0, uint32_t b1)
{
    asm volatile(
        "mma.sync.aligned.m16n8k16.row.col.f32.bf16.bf16.f32 "
        "{%0,%1,%2,%3}, {%4,%5,%6,%7}, {%8,%9}, {%0,%1,%2,%3};"
        : "+f"(c[0]), "+f"(c[1]), "+f"(c[2]), "+f"(c[3])
        : "r"(a[0]), "r"(a[1]), "r"(a[2]), "r"(a[3]), "r"(b0), "r"(b1));
}

__device__ __forceinline__ void mma_s8(int* d, const uint32_t* a, uint32_t b0, uint32_t b1)
{
    asm volatile(
        "mma.sync.aligned.m16n8k32.row.col.s32.s8.s8.s32 "
        "{%0,%1,%2,%3}, {%4,%5,%6,%7}, {%8,%9}, {%0,%1,%2,%3};"
        : "+r"(d[0]), "+r"(d[1]), "+r"(d[2]), "+r"(d[3])
        : "r"(a[0]), "r"(a[1]), "r"(a[2]), "r"(a[3]), "r"(b0), "r"(b1));
}

__device__ __forceinline__ uint32_t smem_u32(const void* p)
{
    uint32_t a;
    asm("{ .reg .u64 t; cvta.to.shared.u64 t, %1; cvt.u32.u64 %0, t; }" : "=r"(a) : "l"(p));
    return a;
}

__device__ __forceinline__ void cp_async8(uint32_t dst, const void* src, int nbytes)
{
    asm volatile("cp.async.ca.shared.global [%0], [%1], 8, %2;"
                 :: "r"(dst), "l"(src), "r"(nbytes) : "memory");
}
#define CP_COMMIT() asm volatile("cp.async.commit_group;" ::: "memory")
#define CP_WAIT0()  asm volatile("cp.async.wait_group 0;" ::: "memory")

// 4-limb balanced base-2^8 decomposition (exact, verified R11)
__device__ __forceinline__ void enc8(float v, float invS, signed char* L)
{
    float u = v * invS;
    float mhf = rintf(u * 65536.f);
    float r = fmaf(mhf, -1.52587890625e-05f, u);
    int ml = (int)rintf(r * 4294967296.f);
    int mh = (int)mhf;
    int d0 = ((ml + 128) & 255) - 128;  ml = (ml - d0) >> 8;
    int d1 = ((ml + 128) & 255) - 128;  mh += (ml - d1) >> 8;
    int d2 = ((mh + 128) & 255) - 128;  mh = (mh - d2) >> 8;
    L[0] = (signed char)mh;
    L[1] = (signed char)d2;
    L[2] = (signed char)d1;
    L[3] = (signed char)d0;
}

// ---------------- prep kernels (verified R11) ----------------
__global__ void fold_enc_kernel(const float* __restrict__ w, const float* __restrict__ bias,
                                const float* __restrict__ g, const float* __restrict__ be,
                                const float* __restrict__ m, const float* __restrict__ v,
                                int8_t* __restrict__ wq, size_t wps,
                                float* __restrict__ bout, int CIN, int COUT)
{
    int idx = blockIdx.x * 256 + threadIdx.x;
    int total = 3 * COUT * CIN;
    if (idx < total) {
        int tap = idx / (COUT * CIN);
        int rem = idx - tap * COUT * CIN;
        int co = rem / CIN;
        int ci = rem - co * CIN;
        float scale = 1.0f;
        if (g) {
            double dinv = (double)g[co] / sqrt((double)v[co] + (double)BN_EPS);
            scale = (float)dinv;
        }
        float val = w[((size_t)co * CIN + ci) * 3 + tap] * scale;
        signed char L[4];
        enc8(val, INV_SW, L);
        #pragma unroll
        for (int p = 0; p < 4; ++p) wq[p * wps + idx] = L[p];
    }
    if (idx < COUT) {
        float bo;
        if (g) {
            double dinv = (double)g[idx] / sqrt((double)v[idx] + (double)BN_EPS);
            bo = (float)((double)bias[idx] * dinv + (double)be[idx] - (double)m[idx] * dinv);
        } else {
            bo = bias[idx];
        }
        bout[idx] = bo;
    }
}

__global__ void esq_kernel(const float* __restrict__ emb)
{
    int j = blockIdx.x * 256 + threadIdx.x;
    if (j < NCODES) {
        const float* e = emb + (size_t)j * C3;
        float s = 0.f;
        #pragma unroll 8
        for (int k = 0; k < C3; ++k) s = fmaf(e[k], e[k], s);
        g_esq[j] = s;
    }
}

__global__ __launch_bounds__(256) void xenc_kernel(const float* __restrict__ x,
                                                   int8_t* __restrict__ q, size_t qps)
{
    __shared__ float tile[32][33];
    int b = blockIdx.z, t0 = blockIdx.x * 32, c0 = blockIdx.y * 32;
    int tx = threadIdx.x & 31, ty = threadIdx.x >> 5;
    #pragma unroll
    for (int i = 0; i < 4; ++i)
        tile[ty + 8 * i][tx] = x[((size_t)b * C0 + c0 + ty + 8 * i) * L0 + t0 + tx];
    __syncthreads();
    int tl = threadIdx.x & 31;
    int c4 = threadIdx.x >> 5;
    signed char L[4][4];
    #pragma unroll
    for (int k = 0; k < 4; ++k) {
        signed char tmp[4];
        enc8(tile[c4 * 4 + k][tl], INV_SX, tmp);
        #pragma unroll
        for (int p = 0; p < 4; ++p) L[p][k] = tmp[p];
    }
    size_t o = ((size_t)b * L0 + t0 + tl) * C0 + c0 + c4 * 4;
    #pragma unroll
    for (int p = 0; p < 4; ++p)
        *(char4*)(q + p * qps + o) = make_char4(L[p][0], L[p][1], L[p][2], L[p][3]);
}

// ---------------- conv via exact int8 IMMA v4: cp.async double-buffered ----------------
// 512 threads / 16 warps (4 warpm x 4 warpn), CTA 128t x 64co, warp m32 x n16.
// Classes 0..3 persistent int32 (exact, verified R11); numerics identical to R11.
// Ping-pong smem buffers; next ci-chunk loaded via cp.async while current computes.
template<int CIN, int LIN, int LOUT, int COUT, int STRIDE, bool RELU, bool SPLITOUT>
__global__ __launch_bounds__(512, 1)
void conv_imma4_kernel(const int8_t* __restrict__ Xq, size_t xps,
                       const int8_t* __restrict__ Wq, size_t wps,
                       const float* __restrict__ bias, float fscale, float invSo,
                       int8_t* __restrict__ Yq, size_t yps,
                       float* __restrict__ Yf)
{
    constexpr int NTR = STRIDE * 128 + 2;
    constexpr int RB = 40;                    // 32 int8 + 8B pad (8B-aligned rows, bank-clean)
    constexpr int ASTR = NTR * RB;
    constexpr int ASZ  = 4 * ASTR;
    constexpr int BSTR = 64 * RB;
    constexpr int BUFSZ = ASZ + 12 * BSTR;
    constexpr int NC = CIN / 32;
    extern __shared__ int8_t smm[];
    const uint32_t smb = smem_u32(smm);

    const int tid = threadIdx.x;
    const int lane = tid & 31;
    const int wid = tid >> 5;
    const int warpm = wid & 3;
    const int warpn = (wid >> 2) & 3;
    const int g = lane >> 2;
    const int tq = lane & 3;
    const int t0  = blockIdx.x * 128;
    const int co0 = blockIdx.y * 64;
    const int bb  = blockIdx.z;
    const int GB  = STRIDE * t0 - 1;

    int ia0[2][2][4], ia1[2][2][4], ia2[2][2][4], ia3[2][2][4];
    #pragma unroll
    for (int mt = 0; mt < 2; ++mt)
        #pragma unroll
        for (int nt = 0; nt < 2; ++nt)
            #pragma unroll
            for (int q = 0; q < 4; ++q) {
                ia0[mt][nt][q] = 0; ia1[mt][nt][q] = 0;
                ia2[mt][nt][q] = 0; ia3[mt][nt][q] = 0;
            }

    // ---- async load issue for chunk cc into buffer base 'dst' ----
    auto issue_loads = [&](int cc, uint32_t dst) {
        // A: NTR rows x 32B x 4 limbs, 8B chunks
        for (int i = tid; i < NTR * 4; i += 512) {
            int r = i >> 2, u = i & 3;
            int grow = GB + r;
            bool ok = (grow >= 0 && grow < LIN);
            size_t boff = ok ? (((size_t)bb * LIN + grow) * CIN + cc * 32) + u * 8 : 0;
            #pragma unroll
            for (int p = 0; p < 4; ++p)
                cp_async8(dst + p * ASTR + r * RB + u * 8, Xq + p * xps + boff, ok ? 8 : 0);
        }
        // B: 3 taps x 64 co x 32B x 4 limbs, 8B chunks
        for (int i = tid; i < 3 * 64 * 4; i += 512) {
            int tap = i >> 8, rem = i & 255;
            int r = rem >> 2, u = rem & 3;
            size_t boff = (((size_t)tap * COUT + co0 + r) * CIN + cc * 32) + u * 8;
            #pragma unroll
            for (int p = 0; p < 4; ++p)
                cp_async8(dst + ASZ + (tap * 4 + p) * BSTR + r * RB + u * 8,
                          Wq + p * wps + boff, 8);
        }
    };

    issue_loads(0, smb);
    CP_COMMIT();
    CP_WAIT0();
    __syncthreads();

    for (int cc = 0; cc < NC; ++cc) {
        if (cc + 1 < NC) {
            issue_loads(cc + 1, smb + ((cc + 1) & 1) * BUFSZ);
            CP_COMMIT();
        }
        const int8_t* sbase = smm + (cc & 1) * BUFSZ;

        #pragma unroll
        for (int tap = 0; tap < 3; ++tap) {
            uint32_t af[4][2][4];
            #pragma unroll
            for (int mt = 0; mt < 2; ++mt) {
                int tl = warpm * 32 + mt * 16 + g;
                int ra = STRIDE * tl + tap;
                int ra8 = ra + 8 * STRIDE;
                #pragma unroll
                for (int p = 0; p < 4; ++p) {
                    const int8_t* base = sbase + p * ASTR;
                    af[p][mt][0] = *(const uint32_t*)&base[ra  * RB + tq * 4];
                    af[p][mt][1] = *(const uint32_t*)&base[ra8 * RB + tq * 4];
                    af[p][mt][2] = *(const uint32_t*)&base[ra  * RB + tq * 4 + 16];
                    af[p][mt][3] = *(const uint32_t*)&base[ra8 * RB + tq * 4 + 16];
                }
            }
            #pragma unroll
            for (int nt = 0; nt < 2; ++nt) {
                int rb = warpn * 16 + nt * 8 + g;
                uint32_t bf[4][2];
                #pragma unroll
                for (int p = 0; p < 4; ++p) {
                    const int8_t* base = sbase + ASZ + (tap * 4 + p) * BSTR;
                    bf[p][0] = *(const uint32_t*)&base[rb * RB + tq * 4];
                    bf[p][1] = *(const uint32_t*)&base[rb * RB + tq * 4 + 16];
                }
                // class 0
                mma_s8(ia0[0][nt], af[0][0], bf[0][0], bf[0][1]);
                mma_s8(ia0[1][nt], af[0][1], bf[0][0], bf[0][1]);
                // class 1
                mma_s8(ia1[0][nt], af[0][0], bf[1][0], bf[1][1]);
                mma_s8(ia1[0][nt], af[1][0], bf[0][0], bf[0][1]);
                mma_s8(ia1[1][nt], af[0][1], bf[1][0], bf[1][1]);
                mma_s8(ia1[1][nt], af[1][1], bf[0][0], bf[0][1]);
                // class 2
                mma_s8(ia2[0][nt], af[0][0], bf[2][0], bf[2][1]);
                mma_s8(ia2[0][nt], af[1][0], bf[1][0], bf[1][1]);
                mma_s8(ia2[0][nt], af[2][0], bf[0][0], bf[0][1]);
                mma_s8(ia2[1][nt], af[0][1], bf[2][0], bf[2][1]);
                mma_s8(ia2[1][nt], af[1][1], bf[1][0], bf[1][1]);
                mma_s8(ia2[1][nt], af[2][1], bf[0][0], bf[0][1]);
                // class 3
                mma_s8(ia3[0][nt], af[0][0], bf[3][0], bf[3][1]);
                mma_s8(ia3[0][nt], af[1][0], bf[2][0], bf[2][1]);
                mma_s8(ia3[0][nt], af[2][0], bf[1][0], bf[1][1]);
                mma_s8(ia3[0][nt], af[3][0], bf[0][0], bf[0][1]);
                mma_s8(ia3[1][nt], af[0][1], bf[3][0], bf[3][1]);
                mma_s8(ia3[1][nt], af[1][1], bf[2][0], bf[2][1]);
                mma_s8(ia3[1][nt], af[2][1], bf[1][0], bf[1][1]);
                mma_s8(ia3[1][nt], af[3][1], bf[0][0], bf[0][1]);
            }
        }
        CP_WAIT0();
        __syncthreads();
    }

    // ---- epilogue (identical math to R11) ----
    #pragma unroll
    for (int nt = 0; nt < 2; ++nt) {
        int cog = co0 + warpn * 16 + nt * 8 + tq * 2;
        float b0 = __ldg(&bias[cog]);
        float b1 = __ldg(&bias[cog + 1]);
        #pragma unroll
        for (int mt = 0; mt < 2; ++mt) {
            #pragma unroll
            for (int half = 0; half < 2; ++half) {
                int t = t0 + warpm * 32 + mt * 16 + g + half * 8;
                int q0 = half * 2, q1 = half * 2 + 1;
                float s0 = __int2float_rn(ia0[mt][nt][q0])
                         + __int2float_rn(ia1[mt][nt][q0]) * 0.00390625f
                         + __int2float_rn(ia2[mt][nt][q0]) * 1.52587890625e-05f
                         + __int2float_rn(ia3[mt][nt][q0]) * 5.9604644775390625e-08f;
                float s1 = __int2float_rn(ia0[mt][nt][q1])
                         + __int2float_rn(ia1[mt][nt][q1]) * 0.00390625f
                         + __int2float_rn(ia2[mt][nt][q1]) * 1.52587890625e-05f
                         + __int2float_rn(ia3[mt][nt][q1]) * 5.9604644775390625e-08f;
                float v0 = fmaf(s0, fscale, b0);
                float v1 = fmaf(s1, fscale, b1);
                if (RELU) {
                    v0 = (v0 >= 0.f) ? v0 : 0.01f * v0;
                    v1 = (v1 >= 0.f) ? v1 : 0.01f * v1;
                }
                if (SPLITOUT) {
                    signed char La[4], Lb[4];
                    enc8(v0, invSo, La);
                    enc8(v1, invSo, Lb);
                    size_t o = ((size_t)bb * LOUT + t) * COUT + cog;
                    #pragma unroll
                    for (int p = 0; p < 4; ++p) {
                        unsigned short pk = (unsigned short)((unsigned char)La[p]
                                          | ((unsigned short)(unsigned char)Lb[p] << 8));
                        *(unsigned short*)(Yq + p * yps + o) = pk;
                    }
                } else {
                    *(float2*)(Yf + ((size_t)bb * LOUT + t) * COUT + cog) = make_float2(v0, v1);
                }
            }
        }
    }
}

// ---------------- VQ splits (verified R3) ----------------
__global__ __launch_bounds__(256) void split_z_kernel(const float* __restrict__ zz)
{
    int idx = blockIdx.x * 256 + threadIdx.x;
    int row = idx >> 4, gs = idx & 15;
    const float* zr = zz + (size_t)row * C3 + gs * 8;
    float4 p0 = *(const float4*)zr;
    float4 p1 = *(const float4*)(zr + 4);
    float v[8] = {p0.x, p0.y, p0.z, p0.w, p1.x, p1.y, p1.z, p1.w};
    unsigned short h[8], l[8];
    #pragma unroll
    for (int e = 0; e < 8; ++e) bsplit2(v[e], h[e], l[e]);
    ((uint4*)g_zhi)[(size_t)row * 16 + gs] = pack8u(h);
    ((uint4*)g_zlo)[(size_t)row * 16 + gs] = pack8u(l);
    if (gs == 0) {
        const float* zf = zz + (size_t)row * C3;
        float a = 0.f;
        #pragma unroll 8
        for (int k = 0; k < C3; ++k) a = fmaf(zf[k], zf[k], a);
        g_arow[row] = a;
    }
}

__global__ __launch_bounds__(256) void split_e_kernel(const float* __restrict__ emb)
{
    int idx = blockIdx.x * 256 + threadIdx.x;
    int row = idx >> 4, gs = idx & 15;
    const float* er = emb + (size_t)row * C3 + gs * 8;
    float4 p0 = *(const float4*)er;
    float4 p1 = *(const float4*)(er + 4);
    float v[8] = {p0.x, p0.y, p0.z, p0.w, p1.x, p1.y, p1.z, p1.w};
    unsigned short h[8], l[8];
    #pragma unroll
    for (int e = 0; e < 8; ++e) bsplit2(v[e], h[e], l[e]);
    ((uint4*)g_ehi)[(size_t)row * 16 + gs] = pack8u(h);
    ((uint4*)g_elo)[(size_t)row * 16 + gs] = pack8u(l);
}

// ---------------- VQ on mma.sync (verified R3, unchanged) ----------------
#define ZH_OFF 0
#define ZL_OFF 34816
#define EH_OFF 69632
#define EL_OFF 87040
#define JF_OFF 104448
#define RV_OFF 104960
#define RJ_OFF 105984
#define VQ_DYN 107520
#define ROWPAD 272

__global__ __launch_bounds__(256, 1)
void vq_mma_kernel(const float* __restrict__ esq, const float* __restrict__ arow,
                   const float* __restrict__ emb,
                   float* __restrict__ codes, float* __restrict__ quant)
{
    extern __shared__ char smc[];
    const int tid = threadIdx.x;
    const int lane = tid & 31;
    const int wid = tid >> 5;
    const int warp_m = wid & 3;
    const int warp_n = wid >> 2;
    const int g = lane >> 2;
    const int tq = lane & 3;
    const int n0 = blockIdx.x * 128;
    const int mbase = warp_m * 32;

    for (int i = tid; i < 128 * 32; i += 256) {
        int row = i >> 5, u = i & 31;
        ((uint2*)(smc + ZH_OFF))[row * 34 + u] = ((const uint2*)g_zhi)[(size_t)(n0 + row) * 32 + u];
        ((uint2*)(smc + ZL_OFF))[row * 34 + u] = ((const uint2*)g_zlo)[(size_t)(n0 + row) * 32 + u];
    }

    float aval[4];
    #pragma unroll
    for (int s = 0; s < 4; ++s)
        aval[s] = __ldg(&arow[n0 + mbase + (s >> 1) * 16 + (s & 1) * 8 + g]);

    float best[4] = {3.4e38f, 3.4e38f, 3.4e38f, 3.4e38f};
    int   bj[4]   = {0, 0, 0, 0};

    for (int c = 0; c < 64; ++c) {
        __syncthreads();
        for (int i = tid; i < 64 * 32; i += 256) {
            int row = i >> 5, u = i & 31;
            ((uint2*)(smc + EH_OFF))[row * 34 + u] = ((const uint2*)g_ehi)[(size_t)(c * 64 + row) * 32 + u];
            ((uint2*)(smc + EL_OFF))[row * 34 + u] = ((const uint2*)g_elo)[(size_t)(c * 64 + row) * 32 + u];
        }
        __syncthreads();

        float acc[2][4][4];
        #pragma unroll
        for (int mt = 0; mt < 2; ++mt)
            #pragma unroll
            for (int nt = 0; nt < 4; ++nt)
                #pragma unroll
                for (int q = 0; q < 4; ++q) acc[mt][nt][q] = 0.f;

        #pragma unroll
        for (int ks = 0; ks < 8; ++ks) {
            const int k0 = ks * 16;
            uint32_t ah[2][4], al[2][4];
            #pragma unroll
            for (int mt = 0; mt < 2; ++mt) {
                int r0 = mbase + mt * 16 + g;
                int cb = (k0 + tq * 2) * 2;
                ah[mt][0] = *(const uint32_t*)(smc + ZH_OFF + r0 * ROWPAD + cb);
                ah[mt][1] = *(const uint32_t*)(smc + ZH_OFF + (r0 + 8) * ROWPAD + cb);
                ah[mt][2] = *(const uint32_t*)(smc + ZH_OFF + r0 * ROWPAD + cb + 16);
                ah[mt][3] = *(const uint32_t*)(smc + ZH_OFF + (r0 + 8) * ROWPAD + cb + 16);
                al[mt][0] = *(const uint32_t*)(smc + ZL_OFF + r0 * ROWPAD + cb);
                al[mt][1] = *(const uint32_t*)(smc + ZL_OFF + (r0 + 8) * ROWPAD + cb);
                al[mt][2] = *(const uint32_t*)(smc + ZL_OFF + r0 * ROWPAD + cb + 16);
                al[mt][3] = *(const uint32_t*)(smc + ZL_OFF + (r0 + 8) * ROWPAD + cb + 16);
            }
            #pragma unroll
            for (int nt = 0; nt < 4; ++nt) {
                int nrow = warp_n * 32 + nt * 8 + g;
                int cb = (k0 + tq * 2) * 2;
                uint32_t bh0 = *(const uint32_t*)(smc + EH_OFF + nrow * ROWPAD + cb);
                uint32_t bh1 = *(const uint32_t*)(smc + EH_OFF + nrow * ROWPAD + cb + 16);
                uint32_t bl0 = *(const uint32_t*)(smc + EL_OFF + nrow * ROWPAD + cb);
                uint32_t bl1 = *(const uint32_t*)(smc + EL_OFF + nrow * ROWPAD + cb + 16);
                #pragma unroll
                for (int mt = 0; mt < 2; ++mt) {
                    mma_bf16(acc[mt][nt], ah[mt], bh0, bh1);
                    mma_bf16(acc[mt][nt], ah[mt], bl0, bl1);
                    mma_bf16(acc[mt][nt], al[mt], bh0, bh1);
                }
            }
        }

        #pragma unroll
        for (int nt = 0; nt < 4; ++nt) {
            int jb = c * 64 + warp_n * 32 + nt * 8 + tq * 2;
            float e0 = __ldg(&esq[jb]);
            float e1 = __ldg(&esq[jb + 1]);
            #pragma unroll
            for (int mt = 0; mt < 2; ++mt) {
                int s0 = mt * 2, s1 = mt * 2 + 1;
                float d;
                d = (aval[s0] + e0) - 2.0f * acc[mt][nt][0];
                if (d < best[s0]) { best[s0] = d; bj[s0] = jb; }
                d = (aval[s0] + e1) - 2.0f * acc[mt][nt][1];
                if (d < best[s0]) { best[s0] = d; bj[s0] = jb + 1; }
                d = (aval[s1] + e0) - 2.0f * acc[mt][nt][2];
                if (d < best[s1]) { best[s1] = d; bj[s1] = jb; }
                d = (aval[s1] + e1) - 2.0f * acc[mt][nt][3];
                if (d < best[s1]) { best[s1] = d; bj[s1] = jb + 1; }
            }
        }
    }

    #pragma unroll
    for (int s = 0; s < 4; ++s) {
        #pragma unroll
        for (int off = 2; off >= 1; off >>= 1) {
            float ov = __shfl_xor_sync(0xffffffffu, best[s], off);
            int   oj = __shfl_xor_sync(0xffffffffu, bj[s],   off);
            if (ov < best[s] || (ov == best[s] && oj < bj[s])) { best[s] = ov; bj[s] = oj; }
        }
    }
    float* rv = (float*)(smc + RV_OFF);
    int*   rj = (int*)(smc + RJ_OFF);
    if (tq == 0) {
        #pragma unroll
        for (int s = 0; s < 4; ++s) {
            int row = mbase + (s >> 1) * 16 + (s & 1) * 8 + g;
            rv[row * 2 + warp_n] = best[s];
            rj[row * 2 + warp_n] = bj[s];
        }
    }
    __syncthreads();

    int* jf = (int*)(smc + JF_OFF);
    if (tid < 128) {
        float v0 = rv[tid * 2], v1 = rv[tid * 2 + 1];
        int   j0 = rj[tid * 2], j1 = rj[tid * 2 + 1];
        int j = (v1 < v0 || (v1 == v0 && j1 < j0)) ? j1 : j0;
        jf[tid] = j;
        codes[n0 + tid] = (float)j;
    }
    __syncthreads();

    for (int i = tid; i < 128 * 32; i += 256) {
        int row = i >> 5, q = i & 31;
        int j = jf[row];
        float4 v = __ldg((const float4*)emb + (size_t)j * 32 + q);
        ((float4*)quant)[(size_t)(n0 + row) * 32 + q] = v;
    }
}

// ---------------- host launch ----------------
static void* sym(const void* s) { void* p = nullptr; cudaGetSymbolAddress(&p, s); return p; }

#define C12_SMEM (2 * (4 * 258 * 40 + 12 * 64 * 40))   // 144000
#define C3_SMEM  (2 * (4 * 130 * 40 + 12 * 64 * 40))   // 103040

extern "C" void kernel_launch(void* const* d_in, const int* in_sizes, int n_in,
                              void* d_out, int out_size)
{
    const float* x       = (const float*)d_in[0];
    const float* conv1_w = (const float*)d_in[1];
    const float* conv1_b = (const float*)d_in[2];
    const float* bn1_g   = (const float*)d_in[3];
    const float* bn1_b   = (const float*)d_in[4];
    const float* bn1_m   = (const float*)d_in[5];
    const float* bn1_v   = (const float*)d_in[6];
    const float* conv2_w = (const float*)d_in[7];
    const float* conv2_b = (const float*)d_in[8];
    const float* bn2_g   = (const float*)d_in[9];
    const float* bn2_b   = (const float*)d_in[10];
    const float* bn2_m   = (const float*)d_in[11];
    const float* bn2_v   = (const float*)d_in[12];
    const float* conv3_w = (const float*)d_in[13];
    const float* conv3_b = (const float*)d_in[14];
    const float* emb     = (const float*)d_in[15];

    float* bb1 = (float*)sym(g_bb1);
    float* bb2 = (float*)sym(g_bb2);
    float* bb3 = (float*)sym(g_bb3);
    float* zz  = (float*)sym(g_zz);
    float* esq = (float*)sym(g_esq);
    float* arw = (float*)sym(g_arow);
    int8_t* xq  = (int8_t*)sym(g_xq);
    int8_t* h1q = (int8_t*)sym(g_h1q);
    int8_t* h2q = (int8_t*)sym(g_h2q);
    int8_t* w1q = (int8_t*)sym(g_w1q);
    int8_t* w2q = (int8_t*)sym(g_w2q);
    int8_t* w3q = (int8_t*)sym(g_w3q);

    float* out = (float*)d_out;
    float* codes_ptr;
    float* quant_ptr;
    const int FULL = NROWS + NROWS * C3;
    if (out_size >= FULL)            { codes_ptr = out; quant_ptr = out + NROWS; }
    else if (out_size == NROWS * C3) { codes_ptr = (float*)sym(g_dummy_codes); quant_ptr = out; }
    else if (out_size == NROWS)      { codes_ptr = out; quant_ptr = (float*)sym(g_dummy_q); }
    else                             { codes_ptr = out; quant_ptr = out + NROWS; }

    cudaFuncSetAttribute(vq_mma_kernel, cudaFuncAttributeMaxDynamicSharedMemorySize, VQ_DYN);
    cudaFuncSetAttribute((const void*)conv_imma4_kernel<C0, L0, L1, C1, 2, true, true>,
                         cudaFuncAttributeMaxDynamicSharedMemorySize, C12_SMEM);
    cudaFuncSetAttribute((const void*)conv_imma4_kernel<C1, L1, L2, C2, 2, true, true>,
                         cudaFuncAttributeMaxDynamicSharedMemorySize, C12_SMEM);
    cudaFuncSetAttribute((const void*)conv_imma4_kernel<C2, L2, L2, C3, 1, false, false>,
                         cudaFuncAttributeMaxDynamicSharedMemorySize, C3_SMEM);

    // Launch order chosen so the ncu-captured launch (index ~3) is conv1.
    {
        dim3 gx(L0 / 32, C0 / 32, BATCH);
        xenc_kernel<<<gx, 256>>>(x, xq, XQN);                                   // 0
    }
    fold_enc_kernel<<<(3 * C1 * C0 + 255) / 256, 256>>>(conv1_w, conv1_b, bn1_g, bn1_b, bn1_m, bn1_v,
                                                        w1q, W1N, bb1, C0, C1); // 1
    fold_enc_kernel<<<(3 * C2 * C1 + 255) / 256, 256>>>(conv2_w, conv2_b, bn2_g, bn2_b, bn2_m, bn2_v,
                                                        w2q, W2N, bb2, C1, C2); // 2
    {
        dim3 g1(L1 / 128, C1 / 64, BATCH);
        conv_imma4_kernel<C0, L0, L1, C1, 2, true, true><<<g1, 512, C12_SMEM>>>(
            xq, XQN, w1q, W1N, bb1, FSCALE1, INV_SH, h1q, H1N, nullptr);        // 3 <- ncu target
    }
    fold_enc_kernel<<<(3 * C3 * C2 + 255) / 256, 256>>>(conv3_w, conv3_b, nullptr, nullptr, nullptr, nullptr,
                                                        w3q, W3N, bb3, C2, C3); // 4
    esq_kernel<<<(NCODES + 255) / 256, 256>>>(emb);                             // 5
    split_e_kernel<<<(NCODES * 16) / 256, 256>>>(emb);                          // 6
    {
        dim3 g2(L2 / 128, C2 / 64, BATCH);
        conv_imma4_kernel<C1, L1, L2, C2, 2, true, true><<<g2, 512, C12_SMEM>>>(
            h1q, H1N, w2q, W2N, bb2, FSCALE2, INV_SH, h2q, H2N, nullptr);       // 7
    }
    {
        dim3 g3(L2 / 128, C3 / 64, BATCH);
        conv_imma4_kernel<C2, L2, L2, C3, 1, false, false><<<g3, 512, C3_SMEM>>>(
            h2q, H2N, w3q, W3N, bb3, FSCALE3, 0.f, nullptr, 0, zz);             // 8
    }
    split_z_kernel<<<(NROWS * 16) / 256, 256>>>(zz);                            // 9
    vq_mma_kernel<<<NROWS / 128, 256, VQ_DYN>>>(esq, arw, emb, codes_ptr, quant_ptr); // 10
}